// round 6
// baseline (speedup 1.0000x reference)
#include <cuda_runtime.h>
#include <cstdint>

#define HWD 256
#define NTILES 8192      // 8 batches * 32 * 32 tiles of 8x8 pixels

// ---------------- device scratch ----------------
__device__ float g_xbuf[(size_t)8 * HWD * HWD * 48];
__device__ float g_w1t[144 * 256];     // W1 transposed [k][o], tf32-rounded
__device__ unsigned int g_ctr[4];

// ---------------- threefry2x32 (exact JAX, 20 rounds) ----------------
__host__ __device__ __forceinline__ void threefry2x32(
    uint32_t k0, uint32_t k1, uint32_t x0, uint32_t x1, uint32_t& o0, uint32_t& o1) {
  uint32_t ks2 = k0 ^ k1 ^ 0x1BD11BDAu;
  uint32_t v0 = x0 + k0, v1 = x1 + k1;
#define TF_ROTL(v, r) (((v) << (r)) | ((v) >> (32 - (r))))
#define TF_RND(r) { v0 += v1; v1 = TF_ROTL(v1, r); v1 ^= v0; }
  TF_RND(13) TF_RND(15) TF_RND(26) TF_RND(6)
  v0 += k1;  v1 += ks2 + 1u;
  TF_RND(17) TF_RND(29) TF_RND(16) TF_RND(24)
  v0 += ks2; v1 += k0 + 2u;
  TF_RND(13) TF_RND(15) TF_RND(26) TF_RND(6)
  v0 += k0;  v1 += k1 + 3u;
  TF_RND(17) TF_RND(29) TF_RND(16) TF_RND(24)
  v0 += k1;  v1 += ks2 + 4u;
  TF_RND(13) TF_RND(15) TF_RND(26) TF_RND(6)
  v0 += ks2; v1 += k0 + 5u;
#undef TF_RND
#undef TF_ROTL
  o0 = v0; o1 = v1;
}

// ---------------- mma helpers ----------------
__device__ __forceinline__ uint32_t cvt_tf32(float f) {
  uint32_t r; asm("cvt.rna.tf32.f32 %0, %1;" : "=r"(r) : "f"(f)); return r;
}
__device__ __forceinline__ void mma_tf32(float* c, uint32_t a0, uint32_t a1,
                                         uint32_t a2, uint32_t a3,
                                         uint32_t b0, uint32_t b1) {
  asm volatile(
    "mma.sync.aligned.m16n8k8.row.col.f32.tf32.tf32.f32 "
    "{%0,%1,%2,%3},{%4,%5,%6,%7},{%8,%9},{%0,%1,%2,%3};"
    : "+f"(c[0]), "+f"(c[1]), "+f"(c[2]), "+f"(c[3])
    : "r"(a0), "r"(a1), "r"(a2), "r"(a3), "r"(b0), "r"(b1));
}

__global__ void nca_reset() { if (threadIdx.x < 4) g_ctr[threadIdx.x] = 0u; }

__global__ void nca_prep(const float* __restrict__ w1) {
  int i = blockIdx.x * 256 + threadIdx.x;           // i < 36864
  int o = i / 144, k = i % 144;
  g_w1t[k * 256 + o] = __uint_as_float(cvt_tf32(w1[i]));
}

// ---------------- shared memory layout (float offsets) ----------------
#define F_CTRL  0             // 8
#define F_FIRE  8             // 64
#define F_FILT  72            // 864
#define F_HALO  936           // 48*102 = 4896
#define F_P     5832          // 64*164 = 10496   (PST=164 >= 144: no row overflow!)
#define F_H     16328         // 64*260 = 16640
#define F_W2    32968         // 256*56 = 14336
#define F_PART  47304         // 64*50  = 3200
#define SM_FLOATS 50504
#define SMEM_BYTES (SM_FLOATS * sizeof(float))
#define PST 164               // 164 % 32 == 4  -> conflict-free A frags, holds K=144
#define HST 260               // 260 % 32 == 4
#define WST 56                // 56  % 32 == 24 -> conflict-free B frags
#define SPST 50               // partials stride (even for float2)
#define HLS 102

__global__ void __launch_bounds__(512, 1)
nca_step_mma(const float* __restrict__ xin, float* __restrict__ xout,
             const float* __restrict__ filt0, const float* __restrict__ filt1,
             const float* __restrict__ b1g, const float* __restrict__ w2g,
             uint32_t key0, uint32_t key1, int step)
{
  extern __shared__ float sm[];
  float* sfire = sm + F_FIRE;
  float* sfilt = sm + F_FILT;
  float* shalo = sm + F_HALO;
  float* Pb    = sm + F_P;
  float* Hb    = sm + F_H;
  float* sW2   = sm + F_W2;
  float* spart = sm + F_PART;

  const int tid = threadIdx.x;
  const int wid = tid >> 5, lid = tid & 31;
  const int g = lid >> 2, t = lid & 3;

  // ---- per-launch setup ----
  for (int i = tid; i < 864; i += 512) sfilt[i] = (i < 432) ? filt0[i] : filt1[i - 432];
  for (int i = tid; i < 12288; i += 512) {          // w2 [48][256] -> sW2[o][c] tf32
    int c = i >> 8, o = i & 255;
    sW2[o * WST + c] = __uint_as_float(cvt_tf32(w2g[i]));
  }
  // GEMM1 bias regs: warp owns o in [wid*16, wid*16+16)
  float biasr[2][2];
  #pragma unroll
  for (int nb = 0; nb < 2; nb++) {
    biasr[nb][0] = b1g[wid * 16 + nb * 8 + 2 * t];
    biasr[nb][1] = b1g[wid * 16 + nb * 8 + 2 * t + 1];
  }
  // GEMM2 role
  const int mb2 = wid >> 2, nh = (wid >> 1) & 1, kh = wid & 1;
  __syncthreads();

  // ---- persistent tile loop ----
  for (;;) {
    if (tid == 0) {
      unsigned tt = atomicAdd(&g_ctr[step], 1u);
      *(volatile unsigned*)(sm + F_CTRL) = tt;
    }
    __syncthreads();          // publish slot + guard smem reuse vs prev tile
    unsigned tilei = *(volatile unsigned*)(sm + F_CTRL);
    if (tilei >= NTILES) break;

    const int bb = (int)(tilei >> 10);
    const int y0 = (int)((tilei >> 5) & 31) * 8;
    const int x0c = (int)(tilei & 31) * 8;
    const float* xb = xin + (size_t)bb * HWD * HWD * 48;

    // ---- halo [48][10][10] planar, reflect, float4 gmem reads ----
    for (int i = tid; i < 1200; i += 512) {
      int c4 = i % 12, pos = i / 12, row = pos / 10, col = pos % 10;
      int gy = y0 - 1 + row; gy = (gy < 0) ? -gy : ((gy >= HWD) ? 2 * HWD - 2 - gy : gy);
      int gx = x0c - 1 + col; gx = (gx < 0) ? -gx : ((gx >= HWD) ? 2 * HWD - 2 - gx : gx);
      float4 v = *(const float4*)(xb + ((size_t)gy * HWD + gx) * 48 + c4 * 4);
      shalo[(c4 * 4 + 0) * HLS + pos] = v.x;
      shalo[(c4 * 4 + 1) * HLS + pos] = v.y;
      shalo[(c4 * 4 + 2) * HLS + pos] = v.z;
      shalo[(c4 * 4 + 3) * HLS + pos] = v.w;
    }
    __syncthreads();

    // ---- x-copy: P[pix][k<48] (tf32-rounded) ----
    {
      int pix = tid >> 3, ko = (tid & 7) * 6;
      int py = pix >> 3, px = pix & 7;
      int pos = (py + 1) * 10 + px + 1;
      #pragma unroll
      for (int j = 0; j < 6; j++)
        Pb[pix * PST + ko + j] =
            __uint_as_float(cvt_tf32(shalo[(ko + j) * HLS + pos]));
    }
    // ---- depthwise convs: task = (py, kf), 8 px per thread ----
    #pragma unroll
    for (int it = 0; it < 2; it++) {
      int task = it * 512 + tid;                 // < 768 = 8 py * 96 kf
      if (task < 768) {
        int py = task / 96, kf = task % 96;
        const float* cf = sfilt + kf * 9;
        const float* plane = shalo + (kf % 48) * HLS;
        float acc[8] = {0.f,0.f,0.f,0.f,0.f,0.f,0.f,0.f};
        #pragma unroll
        for (int dy = 0; dy < 3; dy++) {
          const float* rp = plane + (py + dy) * 10;
          float v[10];
          #pragma unroll
          for (int q = 0; q < 5; q++) { float2 u = *(const float2*)(rp + 2 * q); v[2*q] = u.x; v[2*q+1] = u.y; }
          #pragma unroll
          for (int dx = 0; dx < 3; dx++) {
            float w = cf[dy * 3 + dx];
            #pragma unroll
            for (int i = 0; i < 8; i++) acc[i] = fmaf(v[i + dx], w, acc[i]);
          }
        }
        int K = 48 + kf;
        #pragma unroll
        for (int i = 0; i < 8; i++)
          Pb[(py * 8 + i) * PST + K] = __uint_as_float(cvt_tf32(acc[i]));
      }
    }
    // ---- fire mask ----
    if (tid < 64) {
      int py = tid >> 3, px = tid & 7;
      uint32_t n = ((uint32_t)bb * HWD + (uint32_t)(y0 + py)) * HWD + (uint32_t)(x0c + px);
      uint32_t r0, r1;
      threefry2x32(key0, key1, 0u, n, r0, r1);
      float u = __uint_as_float(((r0 ^ r1) >> 9) | 0x3f800000u) - 1.0f;
      sfire[tid] = (u > 0.5f) ? 1.0f : 0.0f;
    }
    __syncthreads();

    // ---- GEMM1: warp = N-16 slice, all 64 px; B frags streamed from L2 ----
    {
      float acc[4][2][4];
      #pragma unroll
      for (int mb = 0; mb < 4; mb++)
        #pragma unroll
        for (int nb = 0; nb < 2; nb++)
          #pragma unroll
          for (int e = 0; e < 4; e++) acc[mb][nb][e] = 0.f;

      const float* wbase = g_w1t + wid * 16 + g;   // + k*256 (+nb*8)
      uint32_t bn[2][2];
      #pragma unroll
      for (int nb = 0; nb < 2; nb++) {
        bn[nb][0] = __float_as_uint(wbase[(t    ) * 256 + nb * 8]);
        bn[nb][1] = __float_as_uint(wbase[(t + 4) * 256 + nb * 8]);
      }
      const float* pr0 = Pb + g * PST + t;

      #pragma unroll
      for (int ks = 0; ks < 18; ks++) {
        uint32_t bf[2][2];
        #pragma unroll
        for (int nb = 0; nb < 2; nb++) { bf[nb][0] = bn[nb][0]; bf[nb][1] = bn[nb][1]; }
        if (ks < 17) {
          const float* wk = wbase + (ks + 1) * 8 * 256;
          #pragma unroll
          for (int nb = 0; nb < 2; nb++) {
            bn[nb][0] = __float_as_uint(wk[(t    ) * 256 + nb * 8]);
            bn[nb][1] = __float_as_uint(wk[(t + 4) * 256 + nb * 8]);
          }
        }
        #pragma unroll
        for (int mb = 0; mb < 4; mb++) {
          const float* pr = pr0 + mb * 16 * PST + ks * 8;
          uint32_t a0 = __float_as_uint(pr[0]);
          uint32_t a1 = __float_as_uint(pr[8 * PST]);
          uint32_t a2 = __float_as_uint(pr[4]);
          uint32_t a3 = __float_as_uint(pr[8 * PST + 4]);
          mma_tf32(acc[mb][0], a0, a1, a2, a3, bf[0][0], bf[0][1]);
          mma_tf32(acc[mb][1], a0, a1, a2, a3, bf[1][0], bf[1][1]);
        }
      }
      // epilogue1: bias + leaky + tf32 -> H
      #pragma unroll
      for (int mb = 0; mb < 4; mb++)
        #pragma unroll
        for (int nb = 0; nb < 2; nb++) {
          int row = mb * 16 + g;
          int col = wid * 16 + nb * 8 + 2 * t;
          float v0 = acc[mb][nb][0] + biasr[nb][0];
          float v1 = acc[mb][nb][1] + biasr[nb][1];
          v0 = (v0 > 0.f) ? v0 : 0.01f * v0;
          v1 = (v1 > 0.f) ? v1 : 0.01f * v1;
          *(float2*)&Hb[row * HST + col] = make_float2(
              __uint_as_float(cvt_tf32(v0)), __uint_as_float(cvt_tf32(v1)));
          float v2 = acc[mb][nb][2] + biasr[nb][0];
          float v3 = acc[mb][nb][3] + biasr[nb][1];
          v2 = (v2 > 0.f) ? v2 : 0.01f * v2;
          v3 = (v3 > 0.f) ? v3 : 0.01f * v3;
          *(float2*)&Hb[(row + 8) * HST + col] = make_float2(
              __uint_as_float(cvt_tf32(v2)), __uint_as_float(cvt_tf32(v3)));
        }
    }
    __syncthreads();

    // ---- GEMM2: warp = (mb2, nh, kh); K half = 128 ----
    float acc2[3][4];
    #pragma unroll
    for (int nb = 0; nb < 3; nb++)
      #pragma unroll
      for (int e = 0; e < 4; e++) acc2[nb][e] = 0.f;

    {
      const float* hb = Hb + (mb2 * 16 + g) * HST + kh * 128 + t;
      const float* wb = sW2 + (kh * 128 + t) * WST + nh * 24 + g;
      #pragma unroll 4
      for (int ks = 0; ks < 16; ks++) {
        uint32_t a0 = __float_as_uint(hb[ks * 8]);
        uint32_t a1 = __float_as_uint(hb[8 * HST + ks * 8]);
        uint32_t a2 = __float_as_uint(hb[ks * 8 + 4]);
        uint32_t a3 = __float_as_uint(hb[8 * HST + ks * 8 + 4]);
        #pragma unroll
        for (int nb = 0; nb < 3; nb++) {
          uint32_t b0 = __float_as_uint(wb[ks * 8 * WST + nb * 8]);
          uint32_t b1 = __float_as_uint(wb[(ks * 8 + 4) * WST + nb * 8]);
          mma_tf32(acc2[nb], a0, a1, a2, a3, b0, b1);
        }
      }
    }
    // kh=1 warps publish partials
    if (kh == 1) {
      #pragma unroll
      for (int nb = 0; nb < 3; nb++) {
        int c = nh * 24 + nb * 8 + 2 * t;
        *(float2*)&spart[(mb2 * 16 + g) * SPST + c]     = make_float2(acc2[nb][0], acc2[nb][1]);
        *(float2*)&spart[(mb2 * 16 + g + 8) * SPST + c] = make_float2(acc2[nb][2], acc2[nb][3]);
      }
    }
    __syncthreads();

    // kh=0 warps: reduce + fire + masked residual -> gmem
    if (kh == 0) {
      #pragma unroll
      for (int nb = 0; nb < 3; nb++) {
        int c = nh * 24 + nb * 8 + 2 * t;
        #pragma unroll
        for (int hf = 0; hf < 2; hf++) {
          int pix = mb2 * 16 + g + hf * 8;
          int py = pix >> 3, px = pix & 7;
          float fire = sfire[pix];
          float2 pp = *(const float2*)&spart[pix * SPST + c];
          float d0 = acc2[nb][hf * 2 + 0] + pp.x;
          float d1 = acc2[nb][hf * 2 + 1] + pp.y;
          int pos = (py + 1) * 10 + px + 1;
          float xo0 = shalo[c * HLS + pos];
          float xo1 = shalo[(c + 1) * HLS + pos];
          float o0 = xo0 + ((c     >= 3) ? fire * d0 : 0.f);
          float o1 = xo1 + ((c + 1 >= 3) ? fire * d1 : 0.f);
          float* op = xout + (((size_t)bb * HWD + (y0 + py)) * HWD + (x0c + px)) * 48 + c;
          *(float2*)op = make_float2(o0, o1);
        }
      }
    }
    // loop-top __syncthreads orders next-tile smem writes after these reads
  }
}

// ---------------- launcher ----------------
extern "C" void kernel_launch(void* const* d_in, const int* in_sizes, int n_in,
                              void* d_out, int out_size)
{
  const float* x     = (const float*)d_in[0];
  const float* filt0 = (const float*)d_in[1];
  const float* filt1 = (const float*)d_in[2];
  const float* w1    = (const float*)d_in[3];
  const float* b1    = (const float*)d_in[4];
  const float* w2    = (const float*)d_in[5];

  float* xbuf = nullptr;
  cudaGetSymbolAddress((void**)&xbuf, g_xbuf);
  float* outp = (float*)d_out;

  int nsm = 148;
  cudaDeviceGetAttribute(&nsm, cudaDevAttrMultiProcessorCount, 0);

  cudaFuncSetAttribute(nca_step_mma, cudaFuncAttributeMaxDynamicSharedMemorySize,
                       (int)SMEM_BYTES);

  nca_reset<<<1, 32>>>();
  nca_prep<<<144, 256>>>(w1);

  const float* src = x;
  for (int i = 0; i < 4; i++) {
    uint32_t f0, f1; threefry2x32(0u, 42u, 0u, (uint32_t)i, f0, f1);
    uint32_t a0, a1; threefry2x32(f0, f1, 0u, 0u, a0, a1);
    float* dst = (i & 1) ? outp : xbuf;
    if (i == 3) dst = outp;
    nca_step_mma<<<nsm, 512, SMEM_BYTES>>>(src, dst, filt0, filt1, b1, w2,
                                           a0, a1, i);
    src = dst;
  }
}

// round 7
// speedup vs baseline: 1.0153x; 1.0153x over previous
#include <cuda_runtime.h>
#include <cstdint>

#define HWD 256
#define NTILES 4096      // 8 batches * 16 * 32 tiles of 16x8 pixels

// ---------------- device scratch ----------------
__device__ float g_xbuf[(size_t)8 * HWD * HWD * 48];
__device__ float g_w1t[144 * 256];     // W1^T [k][o], tf32-rounded
__device__ float g_w2t[256 * 48];      // W2^T [o][c], tf32-rounded
__device__ unsigned int g_ctr[4];

// ---------------- threefry2x32 (exact JAX, 20 rounds) ----------------
__host__ __device__ __forceinline__ void threefry2x32(
    uint32_t k0, uint32_t k1, uint32_t x0, uint32_t x1, uint32_t& o0, uint32_t& o1) {
  uint32_t ks2 = k0 ^ k1 ^ 0x1BD11BDAu;
  uint32_t v0 = x0 + k0, v1 = x1 + k1;
#define TF_ROTL(v, r) (((v) << (r)) | ((v) >> (32 - (r))))
#define TF_RND(r) { v0 += v1; v1 = TF_ROTL(v1, r); v1 ^= v0; }
  TF_RND(13) TF_RND(15) TF_RND(26) TF_RND(6)
  v0 += k1;  v1 += ks2 + 1u;
  TF_RND(17) TF_RND(29) TF_RND(16) TF_RND(24)
  v0 += ks2; v1 += k0 + 2u;
  TF_RND(13) TF_RND(15) TF_RND(26) TF_RND(6)
  v0 += k0;  v1 += k1 + 3u;
  TF_RND(17) TF_RND(29) TF_RND(16) TF_RND(24)
  v0 += k1;  v1 += ks2 + 4u;
  TF_RND(13) TF_RND(15) TF_RND(26) TF_RND(6)
  v0 += ks2; v1 += k0 + 5u;
#undef TF_RND
#undef TF_ROTL
  o0 = v0; o1 = v1;
}

// ---------------- mma / async helpers (baseline PTX) ----------------
__device__ __forceinline__ uint32_t cvt_tf32(float f) {
  uint32_t r; asm("cvt.rna.tf32.f32 %0, %1;" : "=r"(r) : "f"(f)); return r;
}
__device__ __forceinline__ void mma_tf32(float* c, uint32_t a0, uint32_t a1,
                                         uint32_t a2, uint32_t a3,
                                         uint32_t b0, uint32_t b1) {
  asm volatile(
    "mma.sync.aligned.m16n8k8.row.col.f32.tf32.tf32.f32 "
    "{%0,%1,%2,%3},{%4,%5,%6,%7},{%8,%9},{%0,%1,%2,%3};"
    : "+f"(c[0]), "+f"(c[1]), "+f"(c[2]), "+f"(c[3])
    : "r"(a0), "r"(a1), "r"(a2), "r"(a3), "r"(b0), "r"(b1));
}
__device__ __forceinline__ uint32_t smem_u32_of(const void* p) {
  uint32_t a;
  asm("{ .reg .u64 t; cvta.to.shared.u64 t, %1; cvt.u32.u64 %0, t; }" : "=r"(a) : "l"(p));
  return a;
}
#define CP_ASYNC16(dst, src) \
  asm volatile("cp.async.ca.shared.global [%0], [%1], 16;" :: "r"(dst), "l"(src))
#define CP_COMMIT() asm volatile("cp.async.commit_group;" ::: "memory")
#define CP_WAIT1()  asm volatile("cp.async.wait_group 1;" ::: "memory")
#define CP_WAIT0()  asm volatile("cp.async.wait_group 0;" ::: "memory")

__global__ void nca_reset() { if (threadIdx.x < 4) g_ctr[threadIdx.x] = 0u; }

__global__ void nca_prep(const float* __restrict__ w1, const float* __restrict__ w2) {
  int i = blockIdx.x * 256 + threadIdx.x;
  if (i < 144 * 256) { int o = i / 144, k = i % 144;
    g_w1t[k * 256 + o] = __uint_as_float(cvt_tf32(w1[i])); }
  if (i < 48 * 256)  { int c = i / 256, o = i % 256;
    g_w2t[o * 48 + c] = __uint_as_float(cvt_tf32(w2[i])); }
}

// ---------------- shared memory layout (float offsets) ----------------
#define F_CTRL  0             // 8
#define F_FIRE  8             // 128
#define F_FILT  136           // 864
#define F_HALO  1000          // 48*180 = 8640
#define F_REG   9640          // union: P[128][148]=18944  /  H[128][260]=33280
#define F_W1R   42920         // ring: 3 * 16 * 264 = 12672
#define SM_FLOATS 55592
#define SMEM_BYTES (SM_FLOATS * sizeof(float))
#define PST 148               // >=144; bank = (20g+t) all-distinct -> conflict-free
#define HST 260               // bank = (4g+t) distinct
#define WCS 264               // W1 chunk stride; bank = (8t+g) distinct
#define CHF (16 * WCS)        // floats per ring stage
#define HPL 180               // halo plane (18*10)

__global__ void __launch_bounds__(512, 1)
nca_step_mma(const float* __restrict__ xin, float* __restrict__ xout,
             const float* __restrict__ filt0, const float* __restrict__ filt1,
             const float* __restrict__ b1g,
             uint32_t key0, uint32_t key1, int step)
{
  extern __shared__ float sm[];
  float* sfire = sm + F_FIRE;
  float* sfilt = sm + F_FILT;
  float* shalo = sm + F_HALO;
  float* Pb    = sm + F_REG;
  float* Hb    = sm + F_REG;     // alias: P dead once GEMM1 accs are in regs
  float* w1r   = sm + F_W1R;
  const uint32_t w1r_u32 = smem_u32_of(w1r);

  const int tid = threadIdx.x;
  const int wid = tid >> 5, lid = tid & 31;
  const int g = lid >> 2, t = lid & 3;

  // GEMM1 role: mq = M-quarter (32 px), ns = N-64 slice
  const int mq = wid & 3, ns = wid >> 2;
  // GEMM2 role: mo = M-16 chunk, nh = N-24 half
  const int mo = wid >> 1, nh = wid & 1;

  // staging role: each thread owns one (row, o8) of a W1 chunk
  const int srow = tid >> 5;                 // 0..15
  const int so0  = (tid & 31) * 8;           // 0..248

  // ---- per-launch setup ----
  for (int i = tid; i < 864; i += 512) sfilt[i] = (i < 432) ? filt0[i] : filt1[i - 432];
  float biasr[8][2];
  #pragma unroll
  for (int nb = 0; nb < 8; nb++) {
    biasr[nb][0] = b1g[ns * 64 + nb * 8 + 2 * t];
    biasr[nb][1] = b1g[ns * 64 + nb * 8 + 2 * t + 1];
  }
  __syncthreads();

  // ---- persistent tile loop ----
  for (;;) {
    if (tid == 0) {
      unsigned tt = atomicAdd(&g_ctr[step], 1u);
      *(volatile unsigned*)(sm + F_CTRL) = tt;
    }
    __syncthreads();          // publish slot + guard smem reuse vs prev tile
    unsigned tilei = *(volatile unsigned*)(sm + F_CTRL);
    if (tilei >= NTILES) break;

    // ---- kick off W1 chunk 0 and 1 (overlaps halo/conv) ----
    #pragma unroll
    for (int j = 0; j < 2; j++) {
      uint32_t dst = w1r_u32 + (uint32_t)((j * CHF + srow * WCS + so0) * 4);
      const float* src = g_w1t + (j * 16 + srow) * 256 + so0;
      CP_ASYNC16(dst, src);
      CP_ASYNC16(dst + 16, src + 4);
      CP_COMMIT();
    }

    const int bb = (int)(tilei >> 9);
    const int y0 = (int)((tilei >> 5) & 15) * 16;
    const int x0c = (int)(tilei & 31) * 8;
    const float* xb = xin + (size_t)bb * HWD * HWD * 48;

    // ---- halo [48][18][10] planar, reflect, float4 gmem reads ----
    for (int i = tid; i < 2160; i += 512) {
      int c4 = i % 12, pos = i / 12, row = pos / 10, col = pos % 10;
      int gy = y0 - 1 + row; gy = (gy < 0) ? -gy : ((gy >= HWD) ? 2 * HWD - 2 - gy : gy);
      int gx = x0c - 1 + col; gx = (gx < 0) ? -gx : ((gx >= HWD) ? 2 * HWD - 2 - gx : gx);
      float4 v = *(const float4*)(xb + ((size_t)gy * HWD + gx) * 48 + c4 * 4);
      shalo[(c4 * 4 + 0) * HPL + pos] = v.x;
      shalo[(c4 * 4 + 1) * HPL + pos] = v.y;
      shalo[(c4 * 4 + 2) * HPL + pos] = v.z;
      shalo[(c4 * 4 + 3) * HPL + pos] = v.w;
    }
    __syncthreads();

    // ---- x-copy: P[pix][k<48] ----
    {
      int pix = tid >> 2, ko = (tid & 3) * 12;
      int py = pix >> 3, px = pix & 7;
      int pos = (py + 1) * 10 + px + 1;
      #pragma unroll
      for (int j = 0; j < 12; j++)
        Pb[pix * PST + ko + j] =
            __uint_as_float(cvt_tf32(shalo[(ko + j) * HPL + pos]));
    }
    // ---- depthwise convs: task = (py 0..15, kf 0..95), 8 px per task ----
    #pragma unroll
    for (int it = 0; it < 3; it++) {
      int task = it * 512 + tid;                 // < 1536
      int py = task / 96, kf = task % 96;
      const float* cf = sfilt + kf * 9;
      const float* plane = shalo + (kf % 48) * HPL;
      float acc[8] = {0.f,0.f,0.f,0.f,0.f,0.f,0.f,0.f};
      #pragma unroll
      for (int dy = 0; dy < 3; dy++) {
        const float* rp = plane + (py + dy) * 10;
        float v[10];
        #pragma unroll
        for (int q = 0; q < 5; q++) { float2 u = *(const float2*)(rp + 2 * q); v[2*q] = u.x; v[2*q+1] = u.y; }
        #pragma unroll
        for (int dx = 0; dx < 3; dx++) {
          float w = cf[dy * 3 + dx];
          #pragma unroll
          for (int i = 0; i < 8; i++) acc[i] = fmaf(v[i + dx], w, acc[i]);
        }
      }
      int K = 48 + kf;
      #pragma unroll
      for (int i = 0; i < 8; i++)
        Pb[(py * 8 + i) * PST + K] = __uint_as_float(cvt_tf32(acc[i]));
    }
    // ---- fire mask (128 px) ----
    if (tid < 128) {
      int py = tid >> 3, px = tid & 7;
      uint32_t n = ((uint32_t)bb * HWD + (uint32_t)(y0 + py)) * HWD + (uint32_t)(x0c + px);
      uint32_t r0, r1;
      threefry2x32(key0, key1, 0u, n, r0, r1);
      float u = __uint_as_float(((r0 ^ r1) >> 9) | 0x3f800000u) - 1.0f;
      sfire[tid] = (u > 0.5f) ? 1.0f : 0.0f;
    }

    // ---- GEMM1: warp = (32 px, 64 o), W1 from cp.async ring ----
    float acc[2][8][4];
    #pragma unroll
    for (int mb = 0; mb < 2; mb++)
      #pragma unroll
      for (int nb = 0; nb < 8; nb++)
        #pragma unroll
        for (int e = 0; e < 4; e++) acc[mb][nb][e] = 0.f;

    const float* pr0 = Pb + (mq * 32 + g) * PST + t;

    for (int c = 0; c < 9; c++) {
      if (c < 8) { CP_WAIT1(); } else { CP_WAIT0(); }
      __syncthreads();                         // chunk c visible; buf (c%3) free
      if (c + 2 <= 8) {
        int j = c + 2;
        uint32_t dst = w1r_u32 + (uint32_t)(((j % 3) * CHF + srow * WCS + so0) * 4);
        const float* src = g_w1t + (j * 16 + srow) * 256 + so0;
        CP_ASYNC16(dst, src);
        CP_ASYNC16(dst + 16, src + 4);
        CP_COMMIT();
      }
      const float* buf = w1r + (c % 3) * CHF + ns * 64;
      #pragma unroll
      for (int ks2 = 0; ks2 < 2; ks2++) {
        const float* brow = buf + (ks2 * 8 + t) * WCS;
        uint32_t bf[8][2];
        #pragma unroll
        for (int nb = 0; nb < 8; nb++) {
          bf[nb][0] = __float_as_uint(brow[nb * 8 + g]);
          bf[nb][1] = __float_as_uint(brow[4 * WCS + nb * 8 + g]);
        }
        const float* pr = pr0 + c * 16 + ks2 * 8;
        #pragma unroll
        for (int mb = 0; mb < 2; mb++) {
          const float* pm = pr + mb * 16 * PST;
          uint32_t a0 = __float_as_uint(pm[0]);
          uint32_t a1 = __float_as_uint(pm[8 * PST]);
          uint32_t a2 = __float_as_uint(pm[4]);
          uint32_t a3 = __float_as_uint(pm[8 * PST + 4]);
          #pragma unroll
          for (int nb = 0; nb < 8; nb++)
            mma_tf32(acc[mb][nb], a0, a1, a2, a3, bf[nb][0], bf[nb][1]);
        }
      }
    }
    __syncthreads();          // all P reads done before H (aliased) writes

    // ---- epilogue1: bias + leaky + tf32 -> H[px][o] ----
    #pragma unroll
    for (int mb = 0; mb < 2; mb++)
      #pragma unroll
      for (int nb = 0; nb < 8; nb++) {
        int row = mq * 32 + mb * 16 + g;
        int col = ns * 64 + nb * 8 + 2 * t;
        float v0 = acc[mb][nb][0] + biasr[nb][0];
        float v1 = acc[mb][nb][1] + biasr[nb][1];
        v0 = (v0 > 0.f) ? v0 : 0.01f * v0;
        v1 = (v1 > 0.f) ? v1 : 0.01f * v1;
        *(float2*)&Hb[row * HST + col] = make_float2(
            __uint_as_float(cvt_tf32(v0)), __uint_as_float(cvt_tf32(v1)));
        float v2 = acc[mb][nb][2] + biasr[nb][0];
        float v3 = acc[mb][nb][3] + biasr[nb][1];
        v2 = (v2 > 0.f) ? v2 : 0.01f * v2;
        v3 = (v3 > 0.f) ? v3 : 0.01f * v3;
        *(float2*)&Hb[(row + 8) * HST + col] = make_float2(
            __uint_as_float(cvt_tf32(v2)), __uint_as_float(cvt_tf32(v3)));
      }
    __syncthreads();          // H ready

    // ---- GEMM2: warp = (16 px, 24 c), full K=256; W2 frags from L2 ----
    float acc2[3][4];
    #pragma unroll
    for (int nb = 0; nb < 3; nb++)
      #pragma unroll
      for (int e = 0; e < 4; e++) acc2[nb][e] = 0.f;

    {
      const float* hb = Hb + (mo * 16 + g) * HST + t;
      const float* wb = g_w2t + nh * 24 + g;
      uint32_t bn[3][2];
      #pragma unroll
      for (int nb = 0; nb < 3; nb++) {
        bn[nb][0] = __float_as_uint(wb[(t    ) * 48 + nb * 8]);
        bn[nb][1] = __float_as_uint(wb[(t + 4) * 48 + nb * 8]);
      }
      #pragma unroll 4
      for (int ks = 0; ks < 32; ks++) {
        uint32_t bf2[3][2];
        #pragma unroll
        for (int nb = 0; nb < 3; nb++) { bf2[nb][0] = bn[nb][0]; bf2[nb][1] = bn[nb][1]; }
        if (ks < 31) {
          const float* wk = wb + (ks + 1) * 8 * 48;
          #pragma unroll
          for (int nb = 0; nb < 3; nb++) {
            bn[nb][0] = __float_as_uint(wk[(t    ) * 48 + nb * 8]);
            bn[nb][1] = __float_as_uint(wk[(t + 4) * 48 + nb * 8]);
          }
        }
        uint32_t a0 = __float_as_uint(hb[ks * 8]);
        uint32_t a1 = __float_as_uint(hb[8 * HST + ks * 8]);
        uint32_t a2 = __float_as_uint(hb[ks * 8 + 4]);
        uint32_t a3 = __float_as_uint(hb[8 * HST + ks * 8 + 4]);
        #pragma unroll
        for (int nb = 0; nb < 3; nb++)
          mma_tf32(acc2[nb], a0, a1, a2, a3, bf2[nb][0], bf2[nb][1]);
      }
    }

    // ---- epilogue2: fire + masked residual -> gmem ----
    #pragma unroll
    for (int nb = 0; nb < 3; nb++) {
      int c = nh * 24 + nb * 8 + 2 * t;
      #pragma unroll
      for (int hf = 0; hf < 2; hf++) {
        int pix = mo * 16 + g + hf * 8;
        int py = pix >> 3, px = pix & 7;
        float fire = sfire[pix];
        float d0 = acc2[nb][hf * 2 + 0];
        float d1 = acc2[nb][hf * 2 + 1];
        int pos = (py + 1) * 10 + px + 1;
        float xo0 = shalo[c * HPL + pos];
        float xo1 = shalo[(c + 1) * HPL + pos];
        float o0 = xo0 + ((c     >= 3) ? fire * d0 : 0.f);
        float o1 = xo1 + ((c + 1 >= 3) ? fire * d1 : 0.f);
        float* op = xout + (((size_t)bb * HWD + (y0 + py)) * HWD + (x0c + px)) * 48 + c;
        *(float2*)op = make_float2(o0, o1);
      }
    }
    // loop-top __syncthreads orders next-tile smem writes after these reads
  }
}

// ---------------- launcher ----------------
extern "C" void kernel_launch(void* const* d_in, const int* in_sizes, int n_in,
                              void* d_out, int out_size)
{
  const float* x     = (const float*)d_in[0];
  const float* filt0 = (const float*)d_in[1];
  const float* filt1 = (const float*)d_in[2];
  const float* w1    = (const float*)d_in[3];
  const float* b1    = (const float*)d_in[4];
  const float* w2    = (const float*)d_in[5];

  float* xbuf = nullptr;
  cudaGetSymbolAddress((void**)&xbuf, g_xbuf);
  float* outp = (float*)d_out;

  int nsm = 148;
  cudaDeviceGetAttribute(&nsm, cudaDevAttrMultiProcessorCount, 0);

  cudaFuncSetAttribute(nca_step_mma, cudaFuncAttributeMaxDynamicSharedMemorySize,
                       (int)SMEM_BYTES);

  nca_reset<<<1, 32>>>();
  nca_prep<<<144, 256>>>(w1, w2);

  const float* src = x;
  for (int i = 0; i < 4; i++) {
    uint32_t f0, f1; threefry2x32(0u, 42u, 0u, (uint32_t)i, f0, f1);
    uint32_t a0, a1; threefry2x32(f0, f1, 0u, 0u, a0, a1);
    float* dst = (i & 1) ? outp : xbuf;
    if (i == 3) dst = outp;
    nca_step_mma<<<nsm, 512, SMEM_BYTES>>>(src, dst, filt0, filt1, b1, a0, a1, i);
    src = dst;
  }
}

// round 8
// speedup vs baseline: 1.1062x; 1.0896x over previous
#include <cuda_runtime.h>
#include <cuda_fp16.h>
#include <cstdint>

#define HWD 256
#define NTILES 8192      // 8 batches * 32 * 32 tiles of 8x8 pixels

// ---------------- device scratch ----------------
__device__ float  g_xbuf[(size_t)8 * HWD * HWD * 48];
__device__ __half g_w1h[256 * 144];    // [o][k] fp16 (same layout as input w1)
__device__ __half g_w2h[48 * 256];     // [c][o] fp16 (same layout as input w2)
__device__ unsigned int g_ctr[4];

// ---------------- threefry2x32 (exact JAX, 20 rounds) ----------------
__host__ __device__ __forceinline__ void threefry2x32(
    uint32_t k0, uint32_t k1, uint32_t x0, uint32_t x1, uint32_t& o0, uint32_t& o1) {
  uint32_t ks2 = k0 ^ k1 ^ 0x1BD11BDAu;
  uint32_t v0 = x0 + k0, v1 = x1 + k1;
#define TF_ROTL(v, r) (((v) << (r)) | ((v) >> (32 - (r))))
#define TF_RND(r) { v0 += v1; v1 = TF_ROTL(v1, r); v1 ^= v0; }
  TF_RND(13) TF_RND(15) TF_RND(26) TF_RND(6)
  v0 += k1;  v1 += ks2 + 1u;
  TF_RND(17) TF_RND(29) TF_RND(16) TF_RND(24)
  v0 += ks2; v1 += k0 + 2u;
  TF_RND(13) TF_RND(15) TF_RND(26) TF_RND(6)
  v0 += k0;  v1 += k1 + 3u;
  TF_RND(17) TF_RND(29) TF_RND(16) TF_RND(24)
  v0 += k1;  v1 += ks2 + 4u;
  TF_RND(13) TF_RND(15) TF_RND(26) TF_RND(6)
  v0 += ks2; v1 += k0 + 5u;
#undef TF_RND
#undef TF_ROTL
  o0 = v0; o1 = v1;
}

// ---------------- mma helper: fp16 inputs, fp32 accumulate ----------------
__device__ __forceinline__ void mma_f16(float* c, uint32_t a0, uint32_t a1,
                                        uint32_t a2, uint32_t a3,
                                        uint32_t b0, uint32_t b1) {
  asm volatile(
    "mma.sync.aligned.m16n8k16.row.col.f32.f16.f16.f32 "
    "{%0,%1,%2,%3},{%4,%5,%6,%7},{%8,%9},{%0,%1,%2,%3};"
    : "+f"(c[0]), "+f"(c[1]), "+f"(c[2]), "+f"(c[3])
    : "r"(a0), "r"(a1), "r"(a2), "r"(a3), "r"(b0), "r"(b1));
}

__global__ void nca_reset() { if (threadIdx.x < 4) g_ctr[threadIdx.x] = 0u; }

__global__ void nca_prep(const float* __restrict__ w1, const float* __restrict__ w2) {
  int i = blockIdx.x * 256 + threadIdx.x;          // < 36864
  if (i < 256 * 144) g_w1h[i] = __float2half_rn(w1[i]);
  if (i < 48 * 256)  g_w2h[i] = __float2half_rn(w2[i]);
}

// ---------------- shared memory layout (float offsets) ----------------
#define F_CTRL  0             // 8
#define F_FIRE  8             // 64
#define F_B1    72            // 256
#define F_FILT  328           // 864
#define F_HALO  1192          // 48*102 = 4896
#define F_PH    6088          // P half[64][152] = 4864 floats
#define F_HH    10952         // H half[64][264] = 8448 floats
#define F_PART  19400         // 64*52 = 3328
#define SM_FLOATS 22728
#define SMEM_BYTES (SM_FLOATS * sizeof(float))
#define PSH 152               // P stride (halfs); words: 76 % 32 == 12 -> conflict-free
#define HSH 264               // H stride (halfs); words: 132 % 32 == 4 -> conflict-free
#define SPST 52               // partials stride (floats)
#define HLS 102               // halo plane stride

__global__ void __launch_bounds__(512, 1)
nca_step_mma(const float* __restrict__ xin, float* __restrict__ xout,
             const float* __restrict__ filt0, const float* __restrict__ filt1,
             const float* __restrict__ b1g,
             uint32_t key0, uint32_t key1, int step)
{
  extern __shared__ float sm[];
  float*  sfire = sm + F_FIRE;
  float*  sb1   = sm + F_B1;
  float*  sfilt = sm + F_FILT;
  float*  shalo = sm + F_HALO;
  __half* Ph    = (__half*)(sm + F_PH);
  __half* Hh    = (__half*)(sm + F_HH);
  float*  spart = sm + F_PART;

  const int tid = threadIdx.x;
  const int wid = tid >> 5, lid = tid & 31;
  const int g = lid >> 2, t = lid & 3;

  // GEMM1 role: ns = N-32 slice (0..7), mh = M-32 half (0..1)
  const int ns = wid & 7, mh = wid >> 3;
  // GEMM2 role: mo = M-16 chunk (0..3), nh = N-24 half, kh = K-128 half
  const int mo = wid & 3, nh = (wid >> 2) & 1, kh = wid >> 3;

  // ---- per-launch setup ----
  for (int i = tid; i < 864; i += 512) sfilt[i] = (i < 432) ? filt0[i] : filt1[i - 432];
  if (tid < 256) sb1[tid] = b1g[tid];
  __syncthreads();

  // ---- persistent tile loop ----
  for (;;) {
    if (tid == 0) {
      unsigned tt = atomicAdd(&g_ctr[step], 1u);
      *(volatile unsigned*)(sm + F_CTRL) = tt;
    }
    __syncthreads();          // publish slot + guard smem reuse vs prev tile
    unsigned tilei = *(volatile unsigned*)(sm + F_CTRL);
    if (tilei >= NTILES) break;

    const int bb = (int)(tilei >> 10);
    const int y0 = (int)((tilei >> 5) & 31) * 8;
    const int x0c = (int)(tilei & 31) * 8;
    const float* xb = xin + (size_t)bb * HWD * HWD * 48;

    // ---- halo [48][10][10] planar, reflect, float4 gmem reads ----
    for (int i = tid; i < 1200; i += 512) {
      int c4 = i % 12, pos = i / 12, row = pos / 10, col = pos % 10;
      int gy = y0 - 1 + row; gy = (gy < 0) ? -gy : ((gy >= HWD) ? 2 * HWD - 2 - gy : gy);
      int gx = x0c - 1 + col; gx = (gx < 0) ? -gx : ((gx >= HWD) ? 2 * HWD - 2 - gx : gx);
      float4 v = *(const float4*)(xb + ((size_t)gy * HWD + gx) * 48 + c4 * 4);
      shalo[(c4 * 4 + 0) * HLS + pos] = v.x;
      shalo[(c4 * 4 + 1) * HLS + pos] = v.y;
      shalo[(c4 * 4 + 2) * HLS + pos] = v.z;
      shalo[(c4 * 4 + 3) * HLS + pos] = v.w;
    }
    __syncthreads();

    // ---- x-copy: P[pix][k<48] fp16 ----
    {
      int pix = tid >> 3, ko = (tid & 7) * 6;
      int py = pix >> 3, px = pix & 7;
      int pos = (py + 1) * 10 + px + 1;
      #pragma unroll
      for (int j = 0; j < 3; j++) {
        float f0 = shalo[(ko + 2 * j    ) * HLS + pos];
        float f1 = shalo[(ko + 2 * j + 1) * HLS + pos];
        *(__half2*)&Ph[pix * PSH + ko + 2 * j] = __floats2half2_rn(f0, f1);
      }
    }
    // ---- depthwise convs: 768 tasks = (py 0..7, kf 0..95), 8 px each ----
    #pragma unroll
    for (int it = 0; it < 2; it++) {
      int task = it * 512 + tid;
      if (task < 768) {
        int py = task / 96, kf = task % 96;
        const float* cf = sfilt + kf * 9;
        const float* plane = shalo + (kf % 48) * HLS;
        float acc[8] = {0.f,0.f,0.f,0.f,0.f,0.f,0.f,0.f};
        #pragma unroll
        for (int dy = 0; dy < 3; dy++) {
          const float* rp = plane + (py + dy) * 10;
          float v[10];
          #pragma unroll
          for (int q = 0; q < 5; q++) { float2 u = *(const float2*)(rp + 2 * q); v[2*q] = u.x; v[2*q+1] = u.y; }
          #pragma unroll
          for (int dx = 0; dx < 3; dx++) {
            float w = cf[dy * 3 + dx];
            #pragma unroll
            for (int i = 0; i < 8; i++) acc[i] = fmaf(v[i + dx], w, acc[i]);
          }
        }
        int K = 48 + kf;
        #pragma unroll
        for (int i = 0; i < 8; i++)
          Ph[(py * 8 + i) * PSH + K] = __float2half_rn(acc[i]);
      }
    }
    // ---- fire mask ----
    if (tid < 64) {
      int py = tid >> 3, px = tid & 7;
      uint32_t n = ((uint32_t)bb * HWD + (uint32_t)(y0 + py)) * HWD + (uint32_t)(x0c + px);
      uint32_t r0, r1;
      threefry2x32(key0, key1, 0u, n, r0, r1);
      float u = __uint_as_float(((r0 ^ r1) >> 9) | 0x3f800000u) - 1.0f;
      sfire[tid] = (u > 0.5f) ? 1.0f : 0.0f;
    }
    __syncthreads();

    // ---- GEMM1: warp = (N-32 x M-32), K=144 in 9 ksteps of 16 ----
    {
      float acc[2][4][4];
      #pragma unroll
      for (int mc = 0; mc < 2; mc++)
        #pragma unroll
        for (int nb = 0; nb < 4; nb++)
          #pragma unroll
          for (int e = 0; e < 4; e++) acc[mc][nb][e] = 0.f;

      const __half* w1p = g_w1h + (ns * 32 + g) * 144;     // + nb*8*144 + k
      const __half* pr0 = Ph + (mh * 32 + g) * PSH + 2 * t;

      uint32_t bn[4][2];
      #pragma unroll
      for (int nb = 0; nb < 4; nb++) {
        bn[nb][0] = *(const uint32_t*)(w1p + nb * 8 * 144 + 2 * t);
        bn[nb][1] = *(const uint32_t*)(w1p + nb * 8 * 144 + 2 * t + 8);
      }

      #pragma unroll
      for (int ks = 0; ks < 9; ks++) {
        uint32_t bf[4][2];
        #pragma unroll
        for (int nb = 0; nb < 4; nb++) { bf[nb][0] = bn[nb][0]; bf[nb][1] = bn[nb][1]; }
        if (ks < 8) {
          const __half* wk = w1p + (ks + 1) * 16 + 2 * t;
          #pragma unroll
          for (int nb = 0; nb < 4; nb++) {
            bn[nb][0] = *(const uint32_t*)(wk + nb * 8 * 144);
            bn[nb][1] = *(const uint32_t*)(wk + nb * 8 * 144 + 8);
          }
        }
        #pragma unroll
        for (int mc = 0; mc < 2; mc++) {
          const __half* pm = pr0 + mc * 16 * PSH + ks * 16;
          uint32_t a0 = *(const uint32_t*)pm;
          uint32_t a1 = *(const uint32_t*)(pm + 8 * PSH);
          uint32_t a2 = *(const uint32_t*)(pm + 8);
          uint32_t a3 = *(const uint32_t*)(pm + 8 * PSH + 8);
          #pragma unroll
          for (int nb = 0; nb < 4; nb++)
            mma_f16(acc[mc][nb], a0, a1, a2, a3, bf[nb][0], bf[nb][1]);
        }
      }

      // epilogue1: bias + leaky -> H fp16 (P reads done in-warp; H is a
      // separate buffer so no sync needed here)
      #pragma unroll
      for (int mc = 0; mc < 2; mc++)
        #pragma unroll
        for (int nb = 0; nb < 4; nb++) {
          int row = mh * 32 + mc * 16 + g;
          int col = ns * 32 + nb * 8 + 2 * t;
          float b0 = sb1[col], b1v = sb1[col + 1];
          float v0 = acc[mc][nb][0] + b0;
          float v1 = acc[mc][nb][1] + b1v;
          v0 = (v0 > 0.f) ? v0 : 0.01f * v0;
          v1 = (v1 > 0.f) ? v1 : 0.01f * v1;
          *(__half2*)&Hh[row * HSH + col] = __floats2half2_rn(v0, v1);
          float v2 = acc[mc][nb][2] + b0;
          float v3 = acc[mc][nb][3] + b1v;
          v2 = (v2 > 0.f) ? v2 : 0.01f * v2;
          v3 = (v3 > 0.f) ? v3 : 0.01f * v3;
          *(__half2*)&Hh[(row + 8) * HSH + col] = __floats2half2_rn(v2, v3);
        }
    }
    __syncthreads();          // H ready

    // ---- GEMM2: warp = (M-16, N-24, K-128 half); 8 ksteps ----
    float acc2[3][4];
    #pragma unroll
    for (int nb = 0; nb < 3; nb++)
      #pragma unroll
      for (int e = 0; e < 4; e++) acc2[nb][e] = 0.f;

    {
      const __half* hb = Hh + (mo * 16 + g) * HSH + kh * 128 + 2 * t;
      const __half* wb = g_w2h + (nh * 24 + g) * 256 + kh * 128 + 2 * t;
      uint32_t bn2[3][2];
      #pragma unroll
      for (int nb = 0; nb < 3; nb++) {
        bn2[nb][0] = *(const uint32_t*)(wb + nb * 8 * 256);
        bn2[nb][1] = *(const uint32_t*)(wb + nb * 8 * 256 + 8);
      }
      #pragma unroll
      for (int ks = 0; ks < 8; ks++) {
        uint32_t bf2[3][2];
        #pragma unroll
        for (int nb = 0; nb < 3; nb++) { bf2[nb][0] = bn2[nb][0]; bf2[nb][1] = bn2[nb][1]; }
        if (ks < 7) {
          const __half* wk = wb + (ks + 1) * 16;
          #pragma unroll
          for (int nb = 0; nb < 3; nb++) {
            bn2[nb][0] = *(const uint32_t*)(wk + nb * 8 * 256);
            bn2[nb][1] = *(const uint32_t*)(wk + nb * 8 * 256 + 8);
          }
        }
        uint32_t a0 = *(const uint32_t*)(hb + ks * 16);
        uint32_t a1 = *(const uint32_t*)(hb + ks * 16 + 8 * HSH);
        uint32_t a2 = *(const uint32_t*)(hb + ks * 16 + 8);
        uint32_t a3 = *(const uint32_t*)(hb + ks * 16 + 8 * HSH + 8);
        #pragma unroll
        for (int nb = 0; nb < 3; nb++)
          mma_f16(acc2[nb], a0, a1, a2, a3, bf2[nb][0], bf2[nb][1]);
      }
    }

    // kh=1 warps publish partials
    if (kh == 1) {
      #pragma unroll
      for (int nb = 0; nb < 3; nb++) {
        int c = nh * 24 + nb * 8 + 2 * t;
        *(float2*)&spart[(mo * 16 + g) * SPST + c]     = make_float2(acc2[nb][0], acc2[nb][1]);
        *(float2*)&spart[(mo * 16 + g + 8) * SPST + c] = make_float2(acc2[nb][2], acc2[nb][3]);
      }
    }
    __syncthreads();

    // kh=0 warps: reduce + fire + masked residual -> gmem
    if (kh == 0) {
      #pragma unroll
      for (int nb = 0; nb < 3; nb++) {
        int c = nh * 24 + nb * 8 + 2 * t;
        #pragma unroll
        for (int hf = 0; hf < 2; hf++) {
          int pix = mo * 16 + g + hf * 8;
          int py = pix >> 3, px = pix & 7;
          float fire = sfire[pix];
          float2 pp = *(const float2*)&spart[pix * SPST + c];
          float d0 = acc2[nb][hf * 2 + 0] + pp.x;
          float d1 = acc2[nb][hf * 2 + 1] + pp.y;
          int pos = (py + 1) * 10 + px + 1;
          float xo0 = shalo[c * HLS + pos];
          float xo1 = shalo[(c + 1) * HLS + pos];
          float o0 = xo0 + ((c     >= 3) ? fire * d0 : 0.f);
          float o1 = xo1 + ((c + 1 >= 3) ? fire * d1 : 0.f);
          float* op = xout + (((size_t)bb * HWD + (y0 + py)) * HWD + (x0c + px)) * 48 + c;
          *(float2*)op = make_float2(o0, o1);
        }
      }
    }
    // loop-top __syncthreads orders next-tile smem writes after these reads
  }
}

// ---------------- launcher ----------------
extern "C" void kernel_launch(void* const* d_in, const int* in_sizes, int n_in,
                              void* d_out, int out_size)
{
  const float* x     = (const float*)d_in[0];
  const float* filt0 = (const float*)d_in[1];
  const float* filt1 = (const float*)d_in[2];
  const float* w1    = (const float*)d_in[3];
  const float* b1    = (const float*)d_in[4];
  const float* w2    = (const float*)d_in[5];

  float* xbuf = nullptr;
  cudaGetSymbolAddress((void**)&xbuf, g_xbuf);
  float* outp = (float*)d_out;

  int nsm = 148;
  cudaDeviceGetAttribute(&nsm, cudaDevAttrMultiProcessorCount, 0);

  cudaFuncSetAttribute(nca_step_mma, cudaFuncAttributeMaxDynamicSharedMemorySize,
                       (int)SMEM_BYTES);

  nca_reset<<<1, 32>>>();
  nca_prep<<<144, 256>>>(w1, w2);

  const float* src = x;
  for (int i = 0; i < 4; i++) {
    uint32_t f0, f1; threefry2x32(0u, 42u, 0u, (uint32_t)i, f0, f1);
    uint32_t a0, a1; threefry2x32(f0, f1, 0u, 0u, a0, a1);
    float* dst = (i & 1) ? outp : xbuf;
    if (i == 3) dst = outp;
    nca_step_mma<<<nsm, 512, SMEM_BYTES>>>(src, dst, filt0, filt1, b1, a0, a1, i);
    src = dst;
  }
}

// round 9
// speedup vs baseline: 1.8299x; 1.6541x over previous
#include <cuda_runtime.h>
#include <cuda_fp16.h>
#include <cstdint>

#define HWD 256
#define NTILES 8192      // 8 batches * 32 * 32 tiles of 8x8 pixels

// ---------------- device scratch ----------------
__device__ float  g_xbuf[(size_t)8 * HWD * HWD * 48];
__device__ unsigned int g_ctr[4];

// ---------------- threefry2x32 (exact JAX, 20 rounds) ----------------
__host__ __device__ __forceinline__ void threefry2x32(
    uint32_t k0, uint32_t k1, uint32_t x0, uint32_t x1, uint32_t& o0, uint32_t& o1) {
  uint32_t ks2 = k0 ^ k1 ^ 0x1BD11BDAu;
  uint32_t v0 = x0 + k0, v1 = x1 + k1;
#define TF_ROTL(v, r) (((v) << (r)) | ((v) >> (32 - (r))))
#define TF_RND(r) { v0 += v1; v1 = TF_ROTL(v1, r); v1 ^= v0; }
  TF_RND(13) TF_RND(15) TF_RND(26) TF_RND(6)
  v0 += k1;  v1 += ks2 + 1u;
  TF_RND(17) TF_RND(29) TF_RND(16) TF_RND(24)
  v0 += ks2; v1 += k0 + 2u;
  TF_RND(13) TF_RND(15) TF_RND(26) TF_RND(6)
  v0 += k0;  v1 += k1 + 3u;
  TF_RND(17) TF_RND(29) TF_RND(16) TF_RND(24)
  v0 += k1;  v1 += ks2 + 4u;
  TF_RND(13) TF_RND(15) TF_RND(26) TF_RND(6)
  v0 += ks2; v1 += k0 + 5u;
#undef TF_RND
#undef TF_ROTL
  o0 = v0; o1 = v1;
}

// ---------------- helpers ----------------
__device__ __forceinline__ void mma_f16(float* c, uint32_t a0, uint32_t a1,
                                        uint32_t a2, uint32_t a3,
                                        uint32_t b0, uint32_t b1) {
  asm volatile(
    "mma.sync.aligned.m16n8k16.row.col.f32.f16.f16.f32 "
    "{%0,%1,%2,%3},{%4,%5,%6,%7},{%8,%9},{%0,%1,%2,%3};"
    : "+f"(c[0]), "+f"(c[1]), "+f"(c[2]), "+f"(c[3])
    : "r"(a0), "r"(a1), "r"(a2), "r"(a3), "r"(b0), "r"(b1));
}
#define LDMATRIX_X4(r0, r1, r2, r3, addr) \
  asm volatile("ldmatrix.sync.aligned.m8n8.x4.shared.b16 {%0,%1,%2,%3},[%4];" \
    : "=r"(r0), "=r"(r1), "=r"(r2), "=r"(r3) : "r"(addr))
#define LDS_V4(r0, r1, r2, r3, addr) \
  asm volatile("ld.shared.v4.u32 {%0,%1,%2,%3},[%4];" \
    : "=r"(r0), "=r"(r1), "=r"(r2), "=r"(r3) : "r"(addr))
#define LDS_V2(r0, r1, addr) \
  asm volatile("ld.shared.v2.u32 {%0,%1},[%4];" \
    : "=r"(r0), "=r"(r1) : "r"(addr))

__device__ __forceinline__ uint32_t smem_u32_of(const void* p) {
  uint32_t a;
  asm("{ .reg .u64 t; cvta.to.shared.u64 t, %1; cvt.u32.u64 %0, t; }" : "=r"(a) : "l"(p));
  return a;
}
__device__ __forceinline__ uint32_t packh2(float a, float b) {
  __half2 h = __floats2half2_rn(a, b);
  return *(uint32_t*)&h;
}

__global__ void nca_reset() { if (threadIdx.x < 4) g_ctr[threadIdx.x] = 0u; }

// ---------------- shared memory layout (float offsets) ----------------
#define F_CTRL  0             // 8
#define F_FIRE  8             // 64
#define F_B1    72            // 256
#define F_FILT  328           // 864
#define F_HALO  1192          // 48*102 = 4896
#define F_PH    6088          // P half[64][152] = 4864 floats
#define F_HH    10952         // H half[64][264] = 8448 floats
#define F_PART  19400         // 64*52 = 3328
#define F_W1F   22728         // 18432 u32 (9ks x 8ns x 2pr x 32lane x 4)
#define F_W2F   41160         // 12288 u32 (16ks x 2nh x 32lane x 12 [6 used])
#define SM_FLOATS 53448
#define SMEM_BYTES (SM_FLOATS * sizeof(float))
#define PSH 152               // P stride (halfs); 304B rows -> ldmatrix conflict-free
#define HSH 264               // H stride (halfs); 528B rows -> conflict-free
#define SPST 52
#define HLS 102

__global__ void __launch_bounds__(512, 1)
nca_step_mma(const float* __restrict__ xin, float* __restrict__ xout,
             const float* __restrict__ filt0, const float* __restrict__ filt1,
             const float* __restrict__ b1g,
             const float* __restrict__ w1g, const float* __restrict__ w2g,
             uint32_t key0, uint32_t key1, int step)
{
  extern __shared__ float sm[];
  float*  sfire = sm + F_FIRE;
  float*  sb1   = sm + F_B1;
  float*  sfilt = sm + F_FILT;
  float*  shalo = sm + F_HALO;
  __half* Ph    = (__half*)(sm + F_PH);
  __half* Hh    = (__half*)(sm + F_HH);
  float*  spart = sm + F_PART;
  uint32_t* W1F = (uint32_t*)(sm + F_W1F);
  uint32_t* W2F = (uint32_t*)(sm + F_W2F);

  const uint32_t ph_u32  = smem_u32_of(Ph);
  const uint32_t hh_u32  = smem_u32_of(Hh);
  const uint32_t w1f_u32 = smem_u32_of(W1F);
  const uint32_t w2f_u32 = smem_u32_of(W2F);

  const int tid = threadIdx.x;
  const int wid = tid >> 5, lid = tid & 31;
  const int g = lid >> 2, t = lid & 3;

  // GEMM1 role: ns = N-32 slice (0..7), mh = M-32 half (0..1)
  const int ns = wid & 7, mh = wid >> 3;
  // GEMM2 role: mo = M-16 chunk (0..3), nh = N-24 half, kh = K-128 half
  const int mo = wid & 3, nh = (wid >> 2) & 1, kh = wid >> 3;

  // ldmatrix per-lane row mapping
  const int grp = lid >> 3, jj = lid & 7;
  const int rowl = ((grp & 1) << 3) + jj;     // 0..15
  const int koff = (grp >> 1) << 3;           // 0 or 8 (halfs)

  // ---- once-per-launch: filters, bias, weight-fragment packing ----
  for (int i = tid; i < 864; i += 512) sfilt[i] = (i < 432) ? filt0[i] : filt1[i - 432];
  if (tid < 256) sb1[tid] = b1g[tid];

  // W1F: flat = (((ks*8+ns)*2+pr)*32+lane)*4 + r
  for (int idx = tid; idx < 18432; idx += 512) {
    int r = idx & 3, lane = (idx >> 2) & 31, pr = (idx >> 7) & 1, ksns = idx >> 8;
    int ks = ksns >> 3, nss = ksns & 7;
    int gg = lane >> 2, tt = lane & 3;
    int nb = pr * 2 + (r >> 1), j = r & 1;
    int o = nss * 32 + nb * 8 + gg;
    int k = ks * 16 + 2 * tt + j * 8;
    W1F[idx] = packh2(w1g[o * 144 + k], w1g[o * 144 + k + 1]);
  }
  // W2F: region (ks*2+nh): 32 lanes * 12 u32 (6 used)
  for (int f2 = tid; f2 < 6144; f2 += 512) {
    int r = f2 % 6, lane = (f2 / 6) & 31, ksnh = f2 / 192;
    int ks = ksnh >> 1, nhh = ksnh & 1;
    int gg = lane >> 2, tt = lane & 3;
    int nb = r >> 1, j = r & 1;
    int c = nhh * 24 + nb * 8 + gg;
    int k = ks * 16 + 2 * tt + j * 8;
    W2F[ksnh * 384 + lane * 12 + r] = packh2(w2g[c * 256 + k], w2g[c * 256 + k + 1]);
  }
  __syncthreads();

  // GEMM1 A base addresses (ldmatrix), per mc
  uint32_t a1base[2];
  #pragma unroll
  for (int mc = 0; mc < 2; mc++)
    a1base[mc] = ph_u32 + (uint32_t)(((mh * 32 + mc * 16 + rowl) * PSH + koff) * 2);
  // GEMM2 A base
  const uint32_t a2base = hh_u32 + (uint32_t)(((mo * 16 + rowl) * HSH + kh * 128 + koff) * 2);
  // B base addresses
  const uint32_t b1base = w1f_u32 + (uint32_t)(ns * 2 * 512 + lid * 16);   // + ks*8192 + pr*512
  const uint32_t b2base = w2f_u32 + (uint32_t)((kh * 8 * 2 + nh) * 1536 + lid * 48);

  // ---- persistent tile loop ----
  for (;;) {
    if (tid == 0) {
      unsigned tt2 = atomicAdd(&g_ctr[step], 1u);
      *(volatile unsigned*)(sm + F_CTRL) = tt2;
    }
    __syncthreads();
    unsigned tilei = *(volatile unsigned*)(sm + F_CTRL);
    if (tilei >= NTILES) break;

    const int bb = (int)(tilei >> 10);
    const int y0 = (int)((tilei >> 5) & 31) * 8;
    const int x0c = (int)(tilei & 31) * 8;
    const float* xb = xin + (size_t)bb * HWD * HWD * 48;

    // ---- halo [48][10][10] planar + direct interior x -> Ph fp16 ----
    for (int i = tid; i < 1200; i += 512) {
      int c4 = i % 12, pos = i / 12, row = pos / 10, col = pos % 10;
      int gy = y0 - 1 + row; gy = (gy < 0) ? -gy : ((gy >= HWD) ? 2 * HWD - 2 - gy : gy);
      int gx = x0c - 1 + col; gx = (gx < 0) ? -gx : ((gx >= HWD) ? 2 * HWD - 2 - gx : gx);
      float4 v = *(const float4*)(xb + ((size_t)gy * HWD + gx) * 48 + c4 * 4);
      shalo[(c4 * 4 + 0) * HLS + pos] = v.x;
      shalo[(c4 * 4 + 1) * HLS + pos] = v.y;
      shalo[(c4 * 4 + 2) * HLS + pos] = v.z;
      shalo[(c4 * 4 + 3) * HLS + pos] = v.w;
      if (row >= 1 && row <= 8 && col >= 1 && col <= 8) {
        int pix = (row - 1) * 8 + (col - 1);
        uint2 u;
        u.x = packh2(v.x, v.y);
        u.y = packh2(v.z, v.w);
        *(uint2*)&Ph[pix * PSH + c4 * 4] = u;
      }
    }
    __syncthreads();

    // ---- depthwise convs: 768 tasks = (py 0..7, kf 0..95), 8 px each ----
    #pragma unroll
    for (int it = 0; it < 2; it++) {
      int task = it * 512 + tid;
      if (task < 768) {
        int py = task / 96, kf = task % 96;
        const float* cf = sfilt + kf * 9;
        const float* plane = shalo + (kf % 48) * HLS;
        float acc[8] = {0.f,0.f,0.f,0.f,0.f,0.f,0.f,0.f};
        #pragma unroll
        for (int dy = 0; dy < 3; dy++) {
          const float* rp = plane + (py + dy) * 10;
          float v[10];
          #pragma unroll
          for (int q = 0; q < 5; q++) { float2 u = *(const float2*)(rp + 2 * q); v[2*q] = u.x; v[2*q+1] = u.y; }
          #pragma unroll
          for (int dx = 0; dx < 3; dx++) {
            float w = cf[dy * 3 + dx];
            #pragma unroll
            for (int i = 0; i < 8; i++) acc[i] = fmaf(v[i + dx], w, acc[i]);
          }
        }
        int K = 48 + kf;
        #pragma unroll
        for (int i = 0; i < 8; i++)
          Ph[(py * 8 + i) * PSH + K] = __float2half_rn(acc[i]);
      }
    }
    // ---- fire mask ----
    if (tid < 64) {
      int py = tid >> 3, px = tid & 7;
      uint32_t n = ((uint32_t)bb * HWD + (uint32_t)(y0 + py)) * HWD + (uint32_t)(x0c + px);
      uint32_t r0, r1;
      threefry2x32(key0, key1, 0u, n, r0, r1);
      float u = __uint_as_float(((r0 ^ r1) >> 9) | 0x3f800000u) - 1.0f;
      sfire[tid] = (u > 0.5f) ? 1.0f : 0.0f;
    }
    __syncthreads();

    // ---- GEMM1: warp = (N-32 x M-32), 9 ksteps of k16; all operands smem ----
    {
      float acc[2][4][4];
      #pragma unroll
      for (int mc = 0; mc < 2; mc++)
        #pragma unroll
        for (int nb = 0; nb < 4; nb++)
          #pragma unroll
          for (int e = 0; e < 4; e++) acc[mc][nb][e] = 0.f;

      #pragma unroll
      for (int ks = 0; ks < 9; ks++) {
        uint32_t b[4][2];
        LDS_V4(b[0][0], b[0][1], b[1][0], b[1][1], b1base + ks * 8192);
        LDS_V4(b[2][0], b[2][1], b[3][0], b[3][1], b1base + ks * 8192 + 512);
        #pragma unroll
        for (int mc = 0; mc < 2; mc++) {
          uint32_t a0, a1, a2, a3;
          LDMATRIX_X4(a0, a1, a2, a3, a1base[mc] + ks * 32);
          #pragma unroll
          for (int nb = 0; nb < 4; nb++)
            mma_f16(acc[mc][nb], a0, a1, a2, a3, b[nb][0], b[nb][1]);
        }
      }

      // epilogue1: bias + leaky -> H fp16
      #pragma unroll
      for (int mc = 0; mc < 2; mc++)
        #pragma unroll
        for (int nb = 0; nb < 4; nb++) {
          int row = mh * 32 + mc * 16 + g;
          int col = ns * 32 + nb * 8 + 2 * t;
          float b0 = sb1[col], b1v = sb1[col + 1];
          float v0 = acc[mc][nb][0] + b0;
          float v1 = acc[mc][nb][1] + b1v;
          v0 = (v0 > 0.f) ? v0 : 0.01f * v0;
          v1 = (v1 > 0.f) ? v1 : 0.01f * v1;
          *(__half2*)&Hh[row * HSH + col] = __floats2half2_rn(v0, v1);
          float v2 = acc[mc][nb][2] + b0;
          float v3 = acc[mc][nb][3] + b1v;
          v2 = (v2 > 0.f) ? v2 : 0.01f * v2;
          v3 = (v3 > 0.f) ? v3 : 0.01f * v3;
          *(__half2*)&Hh[(row + 8) * HSH + col] = __floats2half2_rn(v2, v3);
        }
    }
    __syncthreads();          // H ready

    // ---- GEMM2: warp = (M-16, N-24, K-128 half); 8 ksteps ----
    float acc2[3][4];
    #pragma unroll
    for (int nb = 0; nb < 3; nb++)
      #pragma unroll
      for (int e = 0; e < 4; e++) acc2[nb][e] = 0.f;

    #pragma unroll
    for (int ks = 0; ks < 8; ks++) {
      uint32_t b2[3][2];
      LDS_V4(b2[0][0], b2[0][1], b2[1][0], b2[1][1], b2base + ks * 3072);
      asm volatile("ld.shared.v2.u32 {%0,%1},[%2];"
        : "=r"(b2[2][0]), "=r"(b2[2][1]) : "r"(b2base + ks * 3072 + 16));
      uint32_t a0, a1, a2, a3;
      LDMATRIX_X4(a0, a1, a2, a3, a2base + ks * 32);
      #pragma unroll
      for (int nb = 0; nb < 3; nb++)
        mma_f16(acc2[nb], a0, a1, a2, a3, b2[nb][0], b2[nb][1]);
    }

    // kh=1 warps publish partials
    if (kh == 1) {
      #pragma unroll
      for (int nb = 0; nb < 3; nb++) {
        int c = nh * 24 + nb * 8 + 2 * t;
        *(float2*)&spart[(mo * 16 + g) * SPST + c]     = make_float2(acc2[nb][0], acc2[nb][1]);
        *(float2*)&spart[(mo * 16 + g + 8) * SPST + c] = make_float2(acc2[nb][2], acc2[nb][3]);
      }
    }
    __syncthreads();

    // kh=0 warps: reduce + fire + masked residual -> gmem
    if (kh == 0) {
      #pragma unroll
      for (int nb = 0; nb < 3; nb++) {
        int c = nh * 24 + nb * 8 + 2 * t;
        #pragma unroll
        for (int hf = 0; hf < 2; hf++) {
          int pix = mo * 16 + g + hf * 8;
          int py = pix >> 3, px = pix & 7;
          float fire = sfire[pix];
          float2 pp = *(const float2*)&spart[pix * SPST + c];
          float d0 = acc2[nb][hf * 2 + 0] + pp.x;
          float d1 = acc2[nb][hf * 2 + 1] + pp.y;
          int pos = (py + 1) * 10 + px + 1;
          float xo0 = shalo[c * HLS + pos];
          float xo1 = shalo[(c + 1) * HLS + pos];
          float o0 = xo0 + ((c     >= 3) ? fire * d0 : 0.f);
          float o1 = xo1 + ((c + 1 >= 3) ? fire * d1 : 0.f);
          float* op = xout + (((size_t)bb * HWD + (y0 + py)) * HWD + (x0c + px)) * 48 + c;
          *(float2*)op = make_float2(o0, o1);
        }
      }
    }
    // loop-top __syncthreads orders next-tile smem writes after these reads
  }
}

// ---------------- launcher ----------------
extern "C" void kernel_launch(void* const* d_in, const int* in_sizes, int n_in,
                              void* d_out, int out_size)
{
  const float* x     = (const float*)d_in[0];
  const float* filt0 = (const float*)d_in[1];
  const float* filt1 = (const float*)d_in[2];
  const float* w1    = (const float*)d_in[3];
  const float* b1    = (const float*)d_in[4];
  const float* w2    = (const float*)d_in[5];

  float* xbuf = nullptr;
  cudaGetSymbolAddress((void**)&xbuf, g_xbuf);
  float* outp = (float*)d_out;

  int nsm = 148;
  cudaDeviceGetAttribute(&nsm, cudaDevAttrMultiProcessorCount, 0);

  cudaFuncSetAttribute(nca_step_mma, cudaFuncAttributeMaxDynamicSharedMemorySize,
                       (int)SMEM_BYTES);

  nca_reset<<<1, 32>>>();

  const float* src = x;
  for (int i = 0; i < 4; i++) {
    uint32_t f0, f1; threefry2x32(0u, 42u, 0u, (uint32_t)i, f0, f1);
    uint32_t a0, a1; threefry2x32(f0, f1, 0u, 0u, a0, a1);
    float* dst = (i & 1) ? outp : xbuf;
    if (i == 3) dst = outp;
    nca_step_mma<<<nsm, 512, SMEM_BYTES>>>(src, dst, filt0, filt1, b1, w1, w2,
                                           a0, a1, i);
    src = dst;
  }
}

// round 11
// speedup vs baseline: 2.0065x; 1.0965x over previous
#include <cuda_runtime.h>
#include <cuda_fp16.h>
#include <cstdint>

#define HWD 256
#define NTILES 8192      // 8 batches * 32 * 32 tiles of 8x8 pixels

// ---------------- device scratch ----------------
__device__ float g_xbuf[(size_t)8 * HWD * HWD * 48];

// ---------------- threefry2x32 (exact JAX, 20 rounds) ----------------
__host__ __device__ __forceinline__ void threefry2x32(
    uint32_t k0, uint32_t k1, uint32_t x0, uint32_t x1, uint32_t& o0, uint32_t& o1) {
  uint32_t ks2 = k0 ^ k1 ^ 0x1BD11BDAu;
  uint32_t v0 = x0 + k0, v1 = x1 + k1;
#define TF_ROTL(v, r) (((v) << (r)) | ((v) >> (32 - (r))))
#define TF_RND(r) { v0 += v1; v1 = TF_ROTL(v1, r); v1 ^= v0; }
  TF_RND(13) TF_RND(15) TF_RND(26) TF_RND(6)
  v0 += k1;  v1 += ks2 + 1u;
  TF_RND(17) TF_RND(29) TF_RND(16) TF_RND(24)
  v0 += ks2; v1 += k0 + 2u;
  TF_RND(13) TF_RND(15) TF_RND(26) TF_RND(6)
  v0 += k0;  v1 += k1 + 3u;
  TF_RND(17) TF_RND(29) TF_RND(16) TF_RND(24)
  v0 += k1;  v1 += ks2 + 4u;
  TF_RND(13) TF_RND(15) TF_RND(26) TF_RND(6)
  v0 += ks2; v1 += k0 + 5u;
#undef TF_RND
#undef TF_ROTL
  o0 = v0; o1 = v1;
}

// ---------------- helpers ----------------
__device__ __forceinline__ void mma_f16(float* c, uint32_t a0, uint32_t a1,
                                        uint32_t a2, uint32_t a3,
                                        uint32_t b0, uint32_t b1) {
  asm volatile(
    "mma.sync.aligned.m16n8k16.row.col.f32.f16.f16.f32 "
    "{%0,%1,%2,%3},{%4,%5,%6,%7},{%8,%9},{%0,%1,%2,%3};"
    : "+f"(c[0]), "+f"(c[1]), "+f"(c[2]), "+f"(c[3])
    : "r"(a0), "r"(a1), "r"(a2), "r"(a3), "r"(b0), "r"(b1));
}
#define LDMATRIX_X4(r0, r1, r2, r3, addr) \
  asm volatile("ldmatrix.sync.aligned.m8n8.x4.shared.b16 {%0,%1,%2,%3},[%4];" \
    : "=r"(r0), "=r"(r1), "=r"(r2), "=r"(r3) : "r"(addr))
#define LDS_V4(r0, r1, r2, r3, addr) \
  asm volatile("ld.shared.v4.u32 {%0,%1,%2,%3},[%4];" \
    : "=r"(r0), "=r"(r1), "=r"(r2), "=r"(r3) : "r"(addr))
#define LDS_V2(r0, r1, addr) \
  asm volatile("ld.shared.v2.u32 {%0,%1},[%2];" \
    : "=r"(r0), "=r"(r1) : "r"(addr))
#define CP_ASYNC16(dst, src) \
  asm volatile("cp.async.ca.shared.global [%0], [%1], 16;" :: "r"(dst), "l"(src))
#define CP_COMMIT() asm volatile("cp.async.commit_group;" ::: "memory")
#define CP_WAIT0()  asm volatile("cp.async.wait_group 0;" ::: "memory")

__device__ __forceinline__ uint32_t smem_u32_of(const void* p) {
  uint32_t a;
  asm("{ .reg .u64 t; cvta.to.shared.u64 t, %1; cvt.u32.u64 %0, t; }" : "=r"(a) : "l"(p));
  return a;
}
__device__ __forceinline__ uint32_t packh2(float a, float b) {
  __half2 h = __floats2half2_rn(a, b);
  return *(uint32_t*)&h;
}

// ---------------- shared memory layout (float offsets) ----------------
// halo staging: [c4 0..11][pos 0..99] float4, stride 100 -> 4800 floats used,
// 4896 allocated per buffer (16B-aligned base: F_HALO*4 = 4768 bytes).
#define F_FIRE  8             // 64
#define F_B1    72            // 256
#define F_FILT  328           // 864
#define F_HALO  1192          // 2 x 4896 = 9792 (double-buffered staging)
#define F_PH    10984         // P half[64][152] = 4864 floats
#define F_HH    15848         // H half[64][264] = 8448 floats
#define F_PART  24296         // 64*52 = 3328
#define F_W1F   27624         // 18432 u32
#define F_W2F   46056         // 6144 u32 (32 regions x 32lane x 6)
#define SM_FLOATS 52200
#define SMEM_BYTES (SM_FLOATS * sizeof(float))
#define PSH 152               // P stride (halfs)
#define HSH 264               // H stride (halfs)
#define SPST 52
#define HALO_F 4896           // floats per halo buffer
#define HPS 100               // halo staging pos-stride (float4 units)

__global__ void __launch_bounds__(512, 1)
nca_step_mma(const float* __restrict__ xin, float* __restrict__ xout,
             const float* __restrict__ filt0, const float* __restrict__ filt1,
             const float* __restrict__ b1g,
             const float* __restrict__ w1g, const float* __restrict__ w2g,
             uint32_t key0, uint32_t key1)
{
  extern __shared__ float sm[];
  float*  sfire = sm + F_FIRE;
  float*  sb1   = sm + F_B1;
  float*  sfilt = sm + F_FILT;
  __half* Ph    = (__half*)(sm + F_PH);
  __half* Hh    = (__half*)(sm + F_HH);
  float*  spart = sm + F_PART;
  uint32_t* W1F = (uint32_t*)(sm + F_W1F);
  uint32_t* W2F = (uint32_t*)(sm + F_W2F);

  const uint32_t ph_u32   = smem_u32_of(Ph);
  const uint32_t hh_u32   = smem_u32_of(Hh);
  const uint32_t w1f_u32  = smem_u32_of(W1F);
  const uint32_t w2f_u32  = smem_u32_of(W2F);
  const uint32_t halo_u32 = smem_u32_of(sm + F_HALO);

  const int tid = threadIdx.x;
  const int wid = tid >> 5, lid = tid & 31;
  const int g = lid >> 2, t = lid & 3;

  // GEMM1 role: ns = N-32 slice (0..7), mh = M-32 half (0..1)
  const int ns = wid & 7, mh = wid >> 3;
  // GEMM2 role: mo = M-16 chunk (0..3), nh = N-24 half, kh = K-128 half
  const int mo = wid & 3, nh = (wid >> 2) & 1, kh = wid >> 3;

  // ldmatrix per-lane row mapping
  const int grp = lid >> 3, jj = lid & 7;
  const int rowl = ((grp & 1) << 3) + jj;
  const int koff = (grp >> 1) << 3;

  // ---- once-per-launch: filters, bias, weight-fragment packing ----
  for (int i = tid; i < 864; i += 512) sfilt[i] = (i < 432) ? filt0[i] : filt1[i - 432];
  if (tid < 256) sb1[tid] = b1g[tid];

  for (int idx = tid; idx < 18432; idx += 512) {
    int r = idx & 3, lane = (idx >> 2) & 31, pr = (idx >> 7) & 1, ksns = idx >> 8;
    int ks = ksns >> 3, nss = ksns & 7;
    int gg = lane >> 2, tt = lane & 3;
    int nb = pr * 2 + (r >> 1), j = r & 1;
    int o = nss * 32 + nb * 8 + gg;
    int k = ks * 16 + 2 * tt + j * 8;
    W1F[idx] = packh2(w1g[o * 144 + k], w1g[o * 144 + k + 1]);
  }
  for (int f2 = tid; f2 < 6144; f2 += 512) {
    int r = f2 % 6, lane = (f2 / 6) & 31, ksnh = f2 / 192;
    int gg = lane >> 2, tt = lane & 3;
    int nb = r >> 1, j = r & 1;
    int c = (ksnh & 1) * 24 + nb * 8 + gg;
    int k = (ksnh >> 1) * 16 + 2 * tt + j * 8;
    W2F[ksnh * 192 + lane * 6 + r] = packh2(w2g[c * 256 + k], w2g[c * 256 + k + 1]);
  }

  uint32_t a1base[2];
  #pragma unroll
  for (int mc = 0; mc < 2; mc++)
    a1base[mc] = ph_u32 + (uint32_t)(((mh * 32 + mc * 16 + rowl) * PSH + koff) * 2);
  const uint32_t a2base = hh_u32 + (uint32_t)(((mo * 16 + rowl) * HSH + kh * 128 + koff) * 2);
  const uint32_t b1base = w1f_u32 + (uint32_t)(ns * 2 * 512 + lid * 16);
  const uint32_t b2base = w2f_u32 + (uint32_t)(((kh * 16 + nh) * 192 + lid * 6) * 4);

  const int niter = (NTILES + (int)gridDim.x - 1) / (int)gridDim.x;

  // ---- prefetch iter-0 halo into buffer 0 ----
  {
    int tile0 = (int)blockIdx.x;
    if (tile0 < NTILES) {
      int bb = tile0 >> 10, y0 = ((tile0 >> 5) & 31) * 8, x0c = (tile0 & 31) * 8;
      const float* xb = xin + (size_t)bb * HWD * HWD * 48;
      for (int i = tid; i < 1200; i += 512) {
        int c4 = i % 12, pos = i / 12, row = pos / 10, col = pos % 10;
        int gy = y0 - 1 + row; gy = (gy < 0) ? -gy : ((gy >= HWD) ? 2 * HWD - 2 - gy : gy);
        int gx = x0c - 1 + col; gx = (gx < 0) ? -gx : ((gx >= HWD) ? 2 * HWD - 2 - gx : gx);
        CP_ASYNC16(halo_u32 + (uint32_t)((c4 * HPS + pos) * 16),
                   xb + ((size_t)gy * HWD + gx) * 48 + c4 * 4);
      }
    }
  }
  CP_COMMIT();
  __syncthreads();   // also publishes weights/filters

  int pb = 0;

  for (int iter = 0; iter < niter; iter++) {
    int tile = iter * (int)gridDim.x + (int)blockIdx.x;
    if (tile >= NTILES) break;

    const int bb = tile >> 10;
    const int y0 = ((tile >> 5) & 31) * 8;
    const int x0c = (tile & 31) * 8;

    CP_WAIT0();
    __syncthreads();            // halo[pb] ready; prev epilogue done

    const float* hstage = sm + F_HALO + pb * HALO_F;

    // ---- x-copy: P[pix][k<48] fp16 (from staged float4) ----
    {
      int pix = tid >> 3, c4 = (tid & 7);
      int py = pix >> 3, px = pix & 7;
      int pos = (py + 1) * 10 + px + 1;
      #pragma unroll
      for (int rep = 0; rep < 2; rep++) {
        int cc4 = c4 + rep * 8;
        if (cc4 < 12) {
          const float4 v = *(const float4*)&hstage[(cc4 * HPS + pos) * 4];
          uint2 u; u.x = packh2(v.x, v.y); u.y = packh2(v.z, v.w);
          *(uint2*)&Ph[pix * PSH + cc4 * 4] = u;
        }
      }
    }
    // ---- depthwise convs: 768 tasks = (py 0..7, kf 0..95), 8 px each ----
    #pragma unroll
    for (int it = 0; it < 2; it++) {
      int task = it * 512 + tid;
      if (task < 768) {
        int py = task / 96, kf = task % 96;
        const float* cf = sfilt + kf * 9;
        int ch = kf % 48, c4 = ch >> 2, ce = ch & 3;
        float acc[8] = {0.f,0.f,0.f,0.f,0.f,0.f,0.f,0.f};
        #pragma unroll
        for (int dy = 0; dy < 3; dy++) {
          float v[10];
          #pragma unroll
          for (int q = 0; q < 10; q++)
            v[q] = hstage[((c4 * HPS + (py + dy) * 10 + q) * 4) + ce];
          #pragma unroll
          for (int dx = 0; dx < 3; dx++) {
            float w = cf[dy * 3 + dx];
            #pragma unroll
            for (int i = 0; i < 8; i++) acc[i] = fmaf(v[i + dx], w, acc[i]);
          }
        }
        int K = 48 + kf;
        #pragma unroll
        for (int i = 0; i < 8; i++)
          Ph[(py * 8 + i) * PSH + K] = __float2half_rn(acc[i]);
      }
    }
    // ---- fire mask ----
    if (tid < 64) {
      int py = tid >> 3, px = tid & 7;
      uint32_t n = ((uint32_t)bb * HWD + (uint32_t)(y0 + py)) * HWD + (uint32_t)(x0c + px);
      uint32_t r0, r1;
      threefry2x32(key0, key1, 0u, n, r0, r1);
      float u = __uint_as_float(((r0 ^ r1) >> 9) | 0x3f800000u) - 1.0f;
      sfire[tid] = (u > 0.5f) ? 1.0f : 0.0f;
    }

    // ---- prefetch next tile's halo into buffer pb^1 (overlaps GEMMs) ----
    {
      int ntile = tile + (int)gridDim.x;
      if (ntile < NTILES) {
        int nbb = ntile >> 10, ny0 = ((ntile >> 5) & 31) * 8, nx0 = (ntile & 31) * 8;
        const float* nxb = xin + (size_t)nbb * HWD * HWD * 48;
        uint32_t dbase = halo_u32 + (uint32_t)((pb ^ 1) * HALO_F * 4);
        for (int i = tid; i < 1200; i += 512) {
          int c4 = i % 12, pos = i / 12, row = pos / 10, col = pos % 10;
          int gy = ny0 - 1 + row; gy = (gy < 0) ? -gy : ((gy >= HWD) ? 2 * HWD - 2 - gy : gy);
          int gx = nx0 - 1 + col; gx = (gx < 0) ? -gx : ((gx >= HWD) ? 2 * HWD - 2 - gx : gx);
          CP_ASYNC16(dbase + (uint32_t)((c4 * HPS + pos) * 16),
                     nxb + ((size_t)gy * HWD + gx) * 48 + c4 * 4);
        }
      }
    }
    CP_COMMIT();
    __syncthreads();            // Ph + fire ready

    // ---- GEMM1: warp = (N-32 x M-32), 9 ksteps of k16 ----
    {
      float acc[2][4][4];
      #pragma unroll
      for (int mc = 0; mc < 2; mc++)
        #pragma unroll
        for (int nb = 0; nb < 4; nb++)
          #pragma unroll
          for (int e = 0; e < 4; e++) acc[mc][nb][e] = 0.f;

      #pragma unroll
      for (int ks = 0; ks < 9; ks++) {
        uint32_t b[4][2];
        LDS_V4(b[0][0], b[0][1], b[1][0], b[1][1], b1base + ks * 8192);
        LDS_V4(b[2][0], b[2][1], b[3][0], b[3][1], b1base + ks * 8192 + 512);
        #pragma unroll
        for (int mc = 0; mc < 2; mc++) {
          uint32_t a0, a1, a2, a3;
          LDMATRIX_X4(a0, a1, a2, a3, a1base[mc] + ks * 32);
          #pragma unroll
          for (int nb = 0; nb < 4; nb++)
            mma_f16(acc[mc][nb], a0, a1, a2, a3, b[nb][0], b[nb][1]);
        }
      }
      // epilogue1: bias + leaky -> H fp16
      #pragma unroll
      for (int mc = 0; mc < 2; mc++)
        #pragma unroll
        for (int nb = 0; nb < 4; nb++) {
          int row = mh * 32 + mc * 16 + g;
          int col = ns * 32 + nb * 8 + 2 * t;
          float b0 = sb1[col], b1v = sb1[col + 1];
          float v0 = acc[mc][nb][0] + b0;
          float v1 = acc[mc][nb][1] + b1v;
          v0 = (v0 > 0.f) ? v0 : 0.01f * v0;
          v1 = (v1 > 0.f) ? v1 : 0.01f * v1;
          *(__half2*)&Hh[row * HSH + col] = __floats2half2_rn(v0, v1);
          float v2 = acc[mc][nb][2] + b0;
          float v3 = acc[mc][nb][3] + b1v;
          v2 = (v2 > 0.f) ? v2 : 0.01f * v2;
          v3 = (v3 > 0.f) ? v3 : 0.01f * v3;
          *(__half2*)&Hh[(row + 8) * HSH + col] = __floats2half2_rn(v2, v3);
        }
    }
    __syncthreads();            // H ready

    // ---- GEMM2: warp = (M-16, N-24, K-128 half); 8 ksteps ----
    float acc2[3][4];
    #pragma unroll
    for (int nb = 0; nb < 3; nb++)
      #pragma unroll
      for (int e = 0; e < 4; e++) acc2[nb][e] = 0.f;

    #pragma unroll
    for (int ks = 0; ks < 8; ks++) {
      uint32_t b2[3][2];
      LDS_V2(b2[0][0], b2[0][1], b2base + ks * 1536);
      LDS_V2(b2[1][0], b2[1][1], b2base + ks * 1536 + 8);
      LDS_V2(b2[2][0], b2[2][1], b2base + ks * 1536 + 16);
      uint32_t a0, a1, a2, a3;
      LDMATRIX_X4(a0, a1, a2, a3, a2base + ks * 32);
      #pragma unroll
      for (int nb = 0; nb < 3; nb++)
        mma_f16(acc2[nb], a0, a1, a2, a3, b2[nb][0], b2[nb][1]);
    }

    // kh=1 warps publish partials
    if (kh == 1) {
      #pragma unroll
      for (int nb = 0; nb < 3; nb++) {
        int c = nh * 24 + nb * 8 + 2 * t;
        *(float2*)&spart[(mo * 16 + g) * SPST + c]     = make_float2(acc2[nb][0], acc2[nb][1]);
        *(float2*)&spart[(mo * 16 + g + 8) * SPST + c] = make_float2(acc2[nb][2], acc2[nb][3]);
      }
    }
    __syncthreads();

    // kh=0 warps: reduce + fire + masked residual -> gmem
    if (kh == 0) {
      #pragma unroll
      for (int nb = 0; nb < 3; nb++) {
        int c = nh * 24 + nb * 8 + 2 * t;
        int c4 = c >> 2, ce = c & 3;
        #pragma unroll
        for (int hf = 0; hf < 2; hf++) {
          int pix = mo * 16 + g + hf * 8;
          int py = pix >> 3, px = pix & 7;
          float fire = sfire[pix];
          float2 pp = *(const float2*)&spart[pix * SPST + c];
          float d0 = acc2[nb][hf * 2 + 0] + pp.x;
          float d1 = acc2[nb][hf * 2 + 1] + pp.y;
          int pos = (py + 1) * 10 + px + 1;
          float xo0 = hstage[(c4 * HPS + pos) * 4 + ce];
          float xo1 = hstage[(c4 * HPS + pos) * 4 + ce + 1];
          float o0 = xo0 + ((c     >= 3) ? fire * d0 : 0.f);
          float o1 = xo1 + ((c + 1 >= 3) ? fire * d1 : 0.f);
          float* op = xout + (((size_t)bb * HWD + (y0 + py)) * HWD + (x0c + px)) * 48 + c;
          *(float2*)op = make_float2(o0, o1);
        }
      }
    }
    pb ^= 1;
    // loop-top wait+sync orders epilogue reads before next prefetch overwrite
  }
}

// ---------------- launcher ----------------
extern "C" void kernel_launch(void* const* d_in, const int* in_sizes, int n_in,
                              void* d_out, int out_size)
{
  const float* x     = (const float*)d_in[0];
  const float* filt0 = (const float*)d_in[1];
  const float* filt1 = (const float*)d_in[2];
  const float* w1    = (const float*)d_in[3];
  const float* b1    = (const float*)d_in[4];
  const float* w2    = (const float*)d_in[5];

  float* xbuf = nullptr;
  cudaGetSymbolAddress((void**)&xbuf, g_xbuf);
  float* outp = (float*)d_out;

  int nsm = 148;
  cudaDeviceGetAttribute(&nsm, cudaDevAttrMultiProcessorCount, 0);

  cudaFuncSetAttribute(nca_step_mma, cudaFuncAttributeMaxDynamicSharedMemorySize,
                       (int)SMEM_BYTES);

  const float* src = x;
  for (int i = 0; i < 4; i++) {
    uint32_t f0, f1; threefry2x32(0u, 42u, 0u, (uint32_t)i, f0, f1);
    uint32_t a0, a1; threefry2x32(f0, f1, 0u, 0u, a0, a1);
    float* dst = (i & 1) ? outp : xbuf;
    if (i == 3) dst = outp;
    nca_step_mma<<<nsm, 512, SMEM_BYTES>>>(src, dst, filt0, filt1, b1, w1, w2,
                                           a0, a1);
    src = dst;
  }
}

// round 12
// speedup vs baseline: 2.4796x; 1.2358x over previous
#include <cuda_runtime.h>
#include <cuda_fp16.h>
#include <cstdint>

#define HWD 256
#define NTILES 8192      // 8 batches * 32 * 32 tiles of 8x8 pixels

// ---------------- device scratch ----------------
__device__ float g_xbuf[(size_t)8 * HWD * HWD * 48];

// ---------------- threefry2x32 (exact JAX, 20 rounds) ----------------
__host__ __device__ __forceinline__ void threefry2x32(
    uint32_t k0, uint32_t k1, uint32_t x0, uint32_t x1, uint32_t& o0, uint32_t& o1) {
  uint32_t ks2 = k0 ^ k1 ^ 0x1BD11BDAu;
  uint32_t v0 = x0 + k0, v1 = x1 + k1;
#define TF_ROTL(v, r) (((v) << (r)) | ((v) >> (32 - (r))))
#define TF_RND(r) { v0 += v1; v1 = TF_ROTL(v1, r); v1 ^= v0; }
  TF_RND(13) TF_RND(15) TF_RND(26) TF_RND(6)
  v0 += k1;  v1 += ks2 + 1u;
  TF_RND(17) TF_RND(29) TF_RND(16) TF_RND(24)
  v0 += ks2; v1 += k0 + 2u;
  TF_RND(13) TF_RND(15) TF_RND(26) TF_RND(6)
  v0 += k0;  v1 += k1 + 3u;
  TF_RND(17) TF_RND(29) TF_RND(16) TF_RND(24)
  v0 += k1;  v1 += ks2 + 4u;
  TF_RND(13) TF_RND(15) TF_RND(26) TF_RND(6)
  v0 += ks2; v1 += k0 + 5u;
#undef TF_RND
#undef TF_ROTL
  o0 = v0; o1 = v1;
}

// ---------------- helpers ----------------
__device__ __forceinline__ void mma_f16(float* c, uint32_t a0, uint32_t a1,
                                        uint32_t a2, uint32_t a3,
                                        uint32_t b0, uint32_t b1) {
  asm volatile(
    "mma.sync.aligned.m16n8k16.row.col.f32.f16.f16.f32 "
    "{%0,%1,%2,%3},{%4,%5,%6,%7},{%8,%9},{%0,%1,%2,%3};"
    : "+f"(c[0]), "+f"(c[1]), "+f"(c[2]), "+f"(c[3])
    : "r"(a0), "r"(a1), "r"(a2), "r"(a3), "r"(b0), "r"(b1));
}
#define LDMATRIX_X4(r0, r1, r2, r3, addr) \
  asm volatile("ldmatrix.sync.aligned.m8n8.x4.shared.b16 {%0,%1,%2,%3},[%4];" \
    : "=r"(r0), "=r"(r1), "=r"(r2), "=r"(r3) : "r"(addr))
#define LDS_V4(r0, r1, r2, r3, addr) \
  asm volatile("ld.shared.v4.u32 {%0,%1,%2,%3},[%4];" \
    : "=r"(r0), "=r"(r1), "=r"(r2), "=r"(r3) : "r"(addr))
#define LDS_V2(r0, r1, addr) \
  asm volatile("ld.shared.v2.u32 {%0,%1},[%2];" \
    : "=r"(r0), "=r"(r1) : "r"(addr))
#define CP_ASYNC16(dst, src) \
  asm volatile("cp.async.ca.shared.global [%0], [%1], 16;" :: "r"(dst), "l"(src))
#define CP_COMMIT() asm volatile("cp.async.commit_group;" ::: "memory")
#define CP_WAIT0()  asm volatile("cp.async.wait_group 0;" ::: "memory")

__device__ __forceinline__ uint32_t smem_u32_of(const void* p) {
  uint32_t a;
  asm("{ .reg .u64 t; cvta.to.shared.u64 t, %1; cvt.u32.u64 %0, t; }" : "=r"(a) : "l"(p));
  return a;
}
__device__ __forceinline__ uint32_t packh2(float a, float b) {
  __half2 h = __floats2half2_rn(a, b);
  return *(uint32_t*)&h;
}

// ---------------- shared memory layout (float offsets) ----------------
// halo staging: [c4 0..11][pos 0..99] float4, pos-stride HPS=105 (ODD:
// c4 bank-stride = 4 -> conv scalar reads are conflict-free for aligned
// warps, 2-way worst-case; was 4-way with HPS=100).
#define F_FIRE  8             // 64
#define F_B1    72            // 256
#define F_FILT  328           // 864
#define F_HALO  1192          // 2 x 5024 = 10048 (double-buffered staging)
#define F_PH    11240         // P half[64][152] = 4864 floats
#define F_HH    16104         // H half[64][264] = 8448 floats
#define F_PART  24552         // 64*52 = 3328
#define F_W1F   27880         // 18432 u32
#define F_W2F   46312         // 6144 u32 (32 regions x 32lane x 6)
#define SM_FLOATS 52456
#define SMEM_BYTES (SM_FLOATS * sizeof(float))
#define PSH 152               // P stride (halfs)
#define HSH 264               // H stride (halfs)
#define SPST 52
#define HALO_F 5024           // floats per halo buffer (used: 5020)
#define HPS 105               // halo staging pos-stride (float4 units)

__global__ void __launch_bounds__(512, 1)
nca_step_mma(const float* __restrict__ xin, float* __restrict__ xout,
             const float* __restrict__ filt0, const float* __restrict__ filt1,
             const float* __restrict__ b1g,
             const float* __restrict__ w1g, const float* __restrict__ w2g,
             uint32_t key0, uint32_t key1)
{
  extern __shared__ float sm[];
  float*  sfire = sm + F_FIRE;
  float*  sb1   = sm + F_B1;
  float*  sfilt = sm + F_FILT;
  __half* Ph    = (__half*)(sm + F_PH);
  __half* Hh    = (__half*)(sm + F_HH);
  float*  spart = sm + F_PART;
  uint32_t* W1F = (uint32_t*)(sm + F_W1F);
  uint32_t* W2F = (uint32_t*)(sm + F_W2F);

  const uint32_t ph_u32   = smem_u32_of(Ph);
  const uint32_t hh_u32   = smem_u32_of(Hh);
  const uint32_t w1f_u32  = smem_u32_of(W1F);
  const uint32_t w2f_u32  = smem_u32_of(W2F);
  const uint32_t halo_u32 = smem_u32_of(sm + F_HALO);

  const int tid = threadIdx.x;
  const int wid = tid >> 5, lid = tid & 31;
  const int g = lid >> 2, t = lid & 3;

  // GEMM1 role: ns = N-32 slice (0..7), mh = M-32 half (0..1)
  const int ns = wid & 7, mh = wid >> 3;
  // GEMM2 role: mo = M-16 chunk (0..3), nh = N-24 half, kh = K-128 half
  const int mo = wid & 3, nh = (wid >> 2) & 1, kh = wid >> 3;

  // ldmatrix per-lane row mapping
  const int grp = lid >> 3, jj = lid & 7;
  const int rowl = ((grp & 1) << 3) + jj;
  const int koff = (grp >> 1) << 3;

  // ---- once-per-launch: filters, bias, weight-fragment packing ----
  for (int i = tid; i < 864; i += 512) sfilt[i] = (i < 432) ? filt0[i] : filt1[i - 432];
  if (tid < 256) sb1[tid] = b1g[tid];

  for (int idx = tid; idx < 18432; idx += 512) {
    int r = idx & 3, lane = (idx >> 2) & 31, pr = (idx >> 7) & 1, ksns = idx >> 8;
    int ks = ksns >> 3, nss = ksns & 7;
    int gg = lane >> 2, tt = lane & 3;
    int nb = pr * 2 + (r >> 1), j = r & 1;
    int o = nss * 32 + nb * 8 + gg;
    int k = ks * 16 + 2 * tt + j * 8;
    W1F[idx] = packh2(w1g[o * 144 + k], w1g[o * 144 + k + 1]);
  }
  for (int f2 = tid; f2 < 6144; f2 += 512) {
    int r = f2 % 6, lane = (f2 / 6) & 31, ksnh = f2 / 192;
    int gg = lane >> 2, tt = lane & 3;
    int nb = r >> 1, j = r & 1;
    int c = (ksnh & 1) * 24 + nb * 8 + gg;
    int k = (ksnh >> 1) * 16 + 2 * tt + j * 8;
    W2F[ksnh * 192 + lane * 6 + r] = packh2(w2g[c * 256 + k], w2g[c * 256 + k + 1]);
  }

  uint32_t a1base[2];
  #pragma unroll
  for (int mc = 0; mc < 2; mc++)
    a1base[mc] = ph_u32 + (uint32_t)(((mh * 32 + mc * 16 + rowl) * PSH + koff) * 2);
  const uint32_t a2base = hh_u32 + (uint32_t)(((mo * 16 + rowl) * HSH + kh * 128 + koff) * 2);
  const uint32_t b1base = w1f_u32 + (uint32_t)(ns * 2 * 512 + lid * 16);
  const uint32_t b2base = w2f_u32 + (uint32_t)(((kh * 16 + nh) * 192 + lid * 6) * 4);

  const int niter = (NTILES + (int)gridDim.x - 1) / (int)gridDim.x;

  // ---- prefetch iter-0 halo into buffer 0 ----
  {
    int tile0 = (int)blockIdx.x;
    if (tile0 < NTILES) {
      int bb = tile0 >> 10, y0 = ((tile0 >> 5) & 31) * 8, x0c = (tile0 & 31) * 8;
      const float* xb = xin + (size_t)bb * HWD * HWD * 48;
      for (int i = tid; i < 1200; i += 512) {
        int c4 = i % 12, pos = i / 12, row = pos / 10, col = pos % 10;
        int gy = y0 - 1 + row; gy = (gy < 0) ? -gy : ((gy >= HWD) ? 2 * HWD - 2 - gy : gy);
        int gx = x0c - 1 + col; gx = (gx < 0) ? -gx : ((gx >= HWD) ? 2 * HWD - 2 - gx : gx);
        CP_ASYNC16(halo_u32 + (uint32_t)((c4 * HPS + pos) * 16),
                   xb + ((size_t)gy * HWD + gx) * 48 + c4 * 4);
      }
    }
  }
  CP_COMMIT();
  __syncthreads();   // also publishes weights/filters

  int pb = 0;

  for (int iter = 0; iter < niter; iter++) {
    int tile = iter * (int)gridDim.x + (int)blockIdx.x;
    if (tile >= NTILES) break;

    const int bb = tile >> 10;
    const int y0 = ((tile >> 5) & 31) * 8;
    const int x0c = (tile & 31) * 8;

    CP_WAIT0();
    __syncthreads();            // halo[pb] ready; prev epilogue done

    const float* hstage = sm + F_HALO + pb * HALO_F;

    // ---- x-copy: P[pix][k<48] fp16 (from staged float4) ----
    {
      int pix = tid >> 3, c4 = (tid & 7);
      int py = pix >> 3, px = pix & 7;
      int pos = (py + 1) * 10 + px + 1;
      #pragma unroll
      for (int rep = 0; rep < 2; rep++) {
        int cc4 = c4 + rep * 8;
        if (cc4 < 12) {
          const float4 v = *(const float4*)&hstage[(cc4 * HPS + pos) * 4];
          uint2 u; u.x = packh2(v.x, v.y); u.y = packh2(v.z, v.w);
          *(uint2*)&Ph[pix * PSH + cc4 * 4] = u;
        }
      }
    }
    // ---- depthwise convs: 768 tasks = (py 0..7, kf 0..95), 8 px each ----
    #pragma unroll
    for (int it = 0; it < 2; it++) {
      int task = it * 512 + tid;
      if (task < 768) {
        int py = task / 96, kf = task % 96;
        const float* cf = sfilt + kf * 9;
        int ch = kf % 48, c4 = ch >> 2, ce = ch & 3;
        float acc[8] = {0.f,0.f,0.f,0.f,0.f,0.f,0.f,0.f};
        #pragma unroll
        for (int dy = 0; dy < 3; dy++) {
          float v[10];
          #pragma unroll
          for (int q = 0; q < 10; q++)
            v[q] = hstage[((c4 * HPS + (py + dy) * 10 + q) * 4) + ce];
          #pragma unroll
          for (int dx = 0; dx < 3; dx++) {
            float w = cf[dy * 3 + dx];
            #pragma unroll
            for (int i = 0; i < 8; i++) acc[i] = fmaf(v[i + dx], w, acc[i]);
          }
        }
        int K = 48 + kf;
        #pragma unroll
        for (int i = 0; i < 8; i++)
          Ph[(py * 8 + i) * PSH + K] = __float2half_rn(acc[i]);
      }
    }
    // ---- fire mask ----
    if (tid < 64) {
      int py = tid >> 3, px = tid & 7;
      uint32_t n = ((uint32_t)bb * HWD + (uint32_t)(y0 + py)) * HWD + (uint32_t)(x0c + px);
      uint32_t r0, r1;
      threefry2x32(key0, key1, 0u, n, r0, r1);
      float u = __uint_as_float(((r0 ^ r1) >> 9) | 0x3f800000u) - 1.0f;
      sfire[tid] = (u > 0.5f) ? 1.0f : 0.0f;
    }

    // ---- prefetch next tile's halo into buffer pb^1 (overlaps GEMMs) ----
    {
      int ntile = tile + (int)gridDim.x;
      if (ntile < NTILES) {
        int nbb = ntile >> 10, ny0 = ((ntile >> 5) & 31) * 8, nx0 = (ntile & 31) * 8;
        const float* nxb = xin + (size_t)nbb * HWD * HWD * 48;
        uint32_t dbase = halo_u32 + (uint32_t)((pb ^ 1) * HALO_F * 4);
        for (int i = tid; i < 1200; i += 512) {
          int c4 = i % 12, pos = i / 12, row = pos / 10, col = pos % 10;
          int gy = ny0 - 1 + row; gy = (gy < 0) ? -gy : ((gy >= HWD) ? 2 * HWD - 2 - gy : gy);
          int gx = nx0 - 1 + col; gx = (gx < 0) ? -gx : ((gx >= HWD) ? 2 * HWD - 2 - gx : gx);
          CP_ASYNC16(dbase + (uint32_t)((c4 * HPS + pos) * 16),
                     nxb + ((size_t)gy * HWD + gx) * 48 + c4 * 4);
        }
      }
    }
    CP_COMMIT();
    __syncthreads();            // Ph + fire ready

    // ---- GEMM1: warp = (N-32 x M-32), 9 ksteps of k16 ----
    {
      float acc[2][4][4];
      #pragma unroll
      for (int mc = 0; mc < 2; mc++)
        #pragma unroll
        for (int nb = 0; nb < 4; nb++)
          #pragma unroll
          for (int e = 0; e < 4; e++) acc[mc][nb][e] = 0.f;

      #pragma unroll
      for (int ks = 0; ks < 9; ks++) {
        uint32_t b[4][2];
        LDS_V4(b[0][0], b[0][1], b[1][0], b[1][1], b1base + ks * 8192);
        LDS_V4(b[2][0], b[2][1], b[3][0], b[3][1], b1base + ks * 8192 + 512);
        #pragma unroll
        for (int mc = 0; mc < 2; mc++) {
          uint32_t a0, a1, a2, a3;
          LDMATRIX_X4(a0, a1, a2, a3, a1base[mc] + ks * 32);
          #pragma unroll
          for (int nb = 0; nb < 4; nb++)
            mma_f16(acc[mc][nb], a0, a1, a2, a3, b[nb][0], b[nb][1]);
        }
      }
      // epilogue1: bias + leaky -> H fp16
      #pragma unroll
      for (int mc = 0; mc < 2; mc++)
        #pragma unroll
        for (int nb = 0; nb < 4; nb++) {
          int row = mh * 32 + mc * 16 + g;
          int col = ns * 32 + nb * 8 + 2 * t;
          float b0 = sb1[col], b1v = sb1[col + 1];
          float v0 = acc[mc][nb][0] + b0;
          float v1 = acc[mc][nb][1] + b1v;
          v0 = (v0 > 0.f) ? v0 : 0.01f * v0;
          v1 = (v1 > 0.f) ? v1 : 0.01f * v1;
          *(__half2*)&Hh[row * HSH + col] = __floats2half2_rn(v0, v1);
          float v2 = acc[mc][nb][2] + b0;
          float v3 = acc[mc][nb][3] + b1v;
          v2 = (v2 > 0.f) ? v2 : 0.01f * v2;
          v3 = (v3 > 0.f) ? v3 : 0.01f * v3;
          *(__half2*)&Hh[(row + 8) * HSH + col] = __floats2half2_rn(v2, v3);
        }
    }
    __syncthreads();            // H ready

    // ---- GEMM2: warp = (M-16, N-24, K-128 half); 8 ksteps ----
    float acc2[3][4];
    #pragma unroll
    for (int nb = 0; nb < 3; nb++)
      #pragma unroll
      for (int e = 0; e < 4; e++) acc2[nb][e] = 0.f;

    #pragma unroll
    for (int ks = 0; ks < 8; ks++) {
      uint32_t b2[3][2];
      LDS_V2(b2[0][0], b2[0][1], b2base + ks * 1536);
      LDS_V2(b2[1][0], b2[1][1], b2base + ks * 1536 + 8);
      LDS_V2(b2[2][0], b2[2][1], b2base + ks * 1536 + 16);
      uint32_t a0, a1, a2, a3;
      LDMATRIX_X4(a0, a1, a2, a3, a2base + ks * 32);
      #pragma unroll
      for (int nb = 0; nb < 3; nb++)
        mma_f16(acc2[nb], a0, a1, a2, a3, b2[nb][0], b2[nb][1]);
    }

    // kh=1 warps publish partials
    if (kh == 1) {
      #pragma unroll
      for (int nb = 0; nb < 3; nb++) {
        int c = nh * 24 + nb * 8 + 2 * t;
        *(float2*)&spart[(mo * 16 + g) * SPST + c]     = make_float2(acc2[nb][0], acc2[nb][1]);
        *(float2*)&spart[(mo * 16 + g + 8) * SPST + c] = make_float2(acc2[nb][2], acc2[nb][3]);
      }
    }
    __syncthreads();

    // kh=0 warps: reduce + fire + masked residual -> gmem
    if (kh == 0) {
      #pragma unroll
      for (int nb = 0; nb < 3; nb++) {
        int c = nh * 24 + nb * 8 + 2 * t;
        int c4 = c >> 2, ce = c & 3;
        #pragma unroll
        for (int hf = 0; hf < 2; hf++) {
          int pix = mo * 16 + g + hf * 8;
          int py = pix >> 3, px = pix & 7;
          float fire = sfire[pix];
          float2 pp = *(const float2*)&spart[pix * SPST + c];
          float d0 = acc2[nb][hf * 2 + 0] + pp.x;
          float d1 = acc2[nb][hf * 2 + 1] + pp.y;
          int pos = (py + 1) * 10 + px + 1;
          float xo0 = hstage[(c4 * HPS + pos) * 4 + ce];
          float xo1 = hstage[(c4 * HPS + pos) * 4 + ce + 1];
          float o0 = xo0 + ((c     >= 3) ? fire * d0 : 0.f);
          float o1 = xo1 + ((c + 1 >= 3) ? fire * d1 : 0.f);
          float* op = xout + (((size_t)bb * HWD + (y0 + py)) * HWD + (x0c + px)) * 48 + c;
          *(float2*)op = make_float2(o0, o1);
        }
      }
    }
    pb ^= 1;
    // loop-top wait+sync orders epilogue reads before next prefetch overwrite
  }
}

// ---------------- launcher ----------------
extern "C" void kernel_launch(void* const* d_in, const int* in_sizes, int n_in,
                              void* d_out, int out_size)
{
  const float* x     = (const float*)d_in[0];
  const float* filt0 = (const float*)d_in[1];
  const float* filt1 = (const float*)d_in[2];
  const float* w1    = (const float*)d_in[3];
  const float* b1    = (const float*)d_in[4];
  const float* w2    = (const float*)d_in[5];

  float* xbuf = nullptr;
  cudaGetSymbolAddress((void**)&xbuf, g_xbuf);
  float* outp = (float*)d_out;

  int nsm = 148;
  cudaDeviceGetAttribute(&nsm, cudaDevAttrMultiProcessorCount, 0);

  cudaFuncSetAttribute(nca_step_mma, cudaFuncAttributeMaxDynamicSharedMemorySize,
                       (int)SMEM_BYTES);

  const float* src = x;
  for (int i = 0; i < 4; i++) {
    uint32_t f0, f1; threefry2x32(0u, 42u, 0u, (uint32_t)i, f0, f1);
    uint32_t a0, a1; threefry2x32(f0, f1, 0u, 0u, a0, a1);
    float* dst = (i & 1) ? outp : xbuf;
    if (i == 3) dst = outp;
    nca_step_mma<<<nsm, 512, SMEM_BYTES>>>(src, dst, filt0, filt1, b1, w1, w2,
                                           a0, a1);
    src = dst;
  }
}

// round 13
// speedup vs baseline: 2.5773x; 1.0394x over previous
#include <cuda_runtime.h>
#include <cuda_fp16.h>
#include <cstdint>

#define HWD 256
#define NTILES 8192      // 8 batches * 32 * 32 tiles of 8x8 pixels

// ---------------- device scratch ----------------
__device__ float g_xbuf[(size_t)8 * HWD * HWD * 48];

// ---------------- threefry2x32 (exact JAX, 20 rounds) ----------------
__host__ __device__ __forceinline__ void threefry2x32(
    uint32_t k0, uint32_t k1, uint32_t x0, uint32_t x1, uint32_t& o0, uint32_t& o1) {
  uint32_t ks2 = k0 ^ k1 ^ 0x1BD11BDAu;
  uint32_t v0 = x0 + k0, v1 = x1 + k1;
#define TF_ROTL(v, r) (((v) << (r)) | ((v) >> (32 - (r))))
#define TF_RND(r) { v0 += v1; v1 = TF_ROTL(v1, r); v1 ^= v0; }
  TF_RND(13) TF_RND(15) TF_RND(26) TF_RND(6)
  v0 += k1;  v1 += ks2 + 1u;
  TF_RND(17) TF_RND(29) TF_RND(16) TF_RND(24)
  v0 += ks2; v1 += k0 + 2u;
  TF_RND(13) TF_RND(15) TF_RND(26) TF_RND(6)
  v0 += k0;  v1 += k1 + 3u;
  TF_RND(17) TF_RND(29) TF_RND(16) TF_RND(24)
  v0 += k1;  v1 += ks2 + 4u;
  TF_RND(13) TF_RND(15) TF_RND(26) TF_RND(6)
  v0 += ks2; v1 += k0 + 5u;
#undef TF_RND
#undef TF_ROTL
  o0 = v0; o1 = v1;
}

// ---------------- helpers ----------------
__device__ __forceinline__ void mma_f16(float* c, uint32_t a0, uint32_t a1,
                                        uint32_t a2, uint32_t a3,
                                        uint32_t b0, uint32_t b1) {
  asm volatile(
    "mma.sync.aligned.m16n8k16.row.col.f32.f16.f16.f32 "
    "{%0,%1,%2,%3},{%4,%5,%6,%7},{%8,%9},{%0,%1,%2,%3};"
    : "+f"(c[0]), "+f"(c[1]), "+f"(c[2]), "+f"(c[3])
    : "r"(a0), "r"(a1), "r"(a2), "r"(a3), "r"(b0), "r"(b1));
}
#define LDMATRIX_X4(r0, r1, r2, r3, addr) \
  asm volatile("ldmatrix.sync.aligned.m8n8.x4.shared.b16 {%0,%1,%2,%3},[%4];" \
    : "=r"(r0), "=r"(r1), "=r"(r2), "=r"(r3) : "r"(addr))
#define LDS_V4(r0, r1, r2, r3, addr) \
  asm volatile("ld.shared.v4.u32 {%0,%1,%2,%3},[%4];" \
    : "=r"(r0), "=r"(r1), "=r"(r2), "=r"(r3) : "r"(addr))
#define LDS_V2(r0, r1, addr) \
  asm volatile("ld.shared.v2.u32 {%0,%1},[%2];" \
    : "=r"(r0), "=r"(r1) : "r"(addr))
#define CP_ASYNC16(dst, src) \
  asm volatile("cp.async.ca.shared.global [%0], [%1], 16;" :: "r"(dst), "l"(src))
#define CP_COMMIT() asm volatile("cp.async.commit_group;" ::: "memory")
#define CP_WAIT0()  asm volatile("cp.async.wait_group 0;" ::: "memory")

__device__ __forceinline__ uint32_t smem_u32_of(const void* p) {
  uint32_t a;
  asm("{ .reg .u64 t; cvta.to.shared.u64 t, %1; cvt.u32.u64 %0, t; }" : "=r"(a) : "l"(p));
  return a;
}
__device__ __forceinline__ uint32_t packh2(float a, float b) {
  __half2 h = __floats2half2_rn(a, b);
  return *(uint32_t*)&h;
}

// ---------------- shared memory layout (float offsets) ----------------
// halo staging: [row 0..9][col 0..9][c4 0..11] float4, row stride HROW=488
// floats (== 8 mod 32 words): conv scalar loads conflict-free for both
// same-row and row+2-mixed warps; col stride 48 (ch-consecutive lanes clean).
#define F_FIRE  8             // 64
#define F_B1    72            // 256
#define F_FILT  328           // 864
#define F_HALO  1192          // 2 x 4880 = 9760 (double-buffered staging)
#define F_PH    10952         // P half[64][152] = 4864 floats
#define F_HH    15816         // H half[64][264] = 8448 floats
#define F_PART  24264         // 64*52 = 3328
#define F_W1F   27592         // 18432 u32
#define F_W2F   46024         // 6144 u32 (32 regions x 32lane x 6)
#define SM_FLOATS 52168
#define SMEM_BYTES (SM_FLOATS * sizeof(float))
#define PSH 152               // P stride (halfs)
#define HSH 264               // H stride (halfs)
#define SPST 52
#define HALO_F 4880           // floats per halo buffer (10 rows x 488)
#define HROW 488              // halo row stride (floats)

__global__ void __launch_bounds__(512, 1)
nca_step_mma(const float* __restrict__ xin, float* __restrict__ xout,
             const float* __restrict__ filt0, const float* __restrict__ filt1,
             const float* __restrict__ b1g,
             const float* __restrict__ w1g, const float* __restrict__ w2g,
             uint32_t key0, uint32_t key1)
{
  extern __shared__ float sm[];
  float*  sfire = sm + F_FIRE;
  float*  sb1   = sm + F_B1;
  float*  sfilt = sm + F_FILT;
  __half* Ph    = (__half*)(sm + F_PH);
  __half* Hh    = (__half*)(sm + F_HH);
  float*  spart = sm + F_PART;
  uint32_t* W1F = (uint32_t*)(sm + F_W1F);
  uint32_t* W2F = (uint32_t*)(sm + F_W2F);

  const uint32_t ph_u32   = smem_u32_of(Ph);
  const uint32_t hh_u32   = smem_u32_of(Hh);
  const uint32_t w1f_u32  = smem_u32_of(W1F);
  const uint32_t w2f_u32  = smem_u32_of(W2F);
  const uint32_t halo_u32 = smem_u32_of(sm + F_HALO);

  const int tid = threadIdx.x;
  const int wid = tid >> 5, lid = tid & 31;
  const int g = lid >> 2, t = lid & 3;

  // GEMM1 role: ns = N-32 slice (0..7), mh = M-32 half (0..1)
  const int ns = wid & 7, mh = wid >> 3;
  // GEMM2 role: mo = M-16 chunk (0..3), nh = N-24 half, kh = K-128 half
  const int mo = wid & 3, nh = (wid >> 2) & 1, kh = wid >> 3;

  // ldmatrix per-lane row mapping
  const int grp = lid >> 3, jj = lid & 7;
  const int rowl = ((grp & 1) << 3) + jj;
  const int koff = (grp >> 1) << 3;

  // ---- once-per-launch: filters, bias, weight-fragment packing ----
  for (int i = tid; i < 864; i += 512) sfilt[i] = (i < 432) ? filt0[i] : filt1[i - 432];
  if (tid < 256) sb1[tid] = b1g[tid];

  for (int idx = tid; idx < 18432; idx += 512) {
    int r = idx & 3, lane = (idx >> 2) & 31, pr = (idx >> 7) & 1, ksns = idx >> 8;
    int ks = ksns >> 3, nss = ksns & 7;
    int gg = lane >> 2, tt = lane & 3;
    int nb = pr * 2 + (r >> 1), j = r & 1;
    int o = nss * 32 + nb * 8 + gg;
    int k = ks * 16 + 2 * tt + j * 8;
    W1F[idx] = packh2(w1g[o * 144 + k], w1g[o * 144 + k + 1]);
  }
  for (int f2 = tid; f2 < 6144; f2 += 512) {
    int r = f2 % 6, lane = (f2 / 6) & 31, ksnh = f2 / 192;
    int gg = lane >> 2, tt = lane & 3;
    int nb = r >> 1, j = r & 1;
    int c = (ksnh & 1) * 24 + nb * 8 + gg;
    int k = (ksnh >> 1) * 16 + 2 * tt + j * 8;
    W2F[ksnh * 192 + lane * 6 + r] = packh2(w2g[c * 256 + k], w2g[c * 256 + k + 1]);
  }

  uint32_t a1base[2];
  #pragma unroll
  for (int mc = 0; mc < 2; mc++)
    a1base[mc] = ph_u32 + (uint32_t)(((mh * 32 + mc * 16 + rowl) * PSH + koff) * 2);
  const uint32_t a2base = hh_u32 + (uint32_t)(((mo * 16 + rowl) * HSH + kh * 128 + koff) * 2);
  const uint32_t b1base = w1f_u32 + (uint32_t)(ns * 2 * 512 + lid * 16);
  const uint32_t b2base = w2f_u32 + (uint32_t)(((kh * 16 + nh) * 192 + lid * 6) * 4);

  const int niter = (NTILES + (int)gridDim.x - 1) / (int)gridDim.x;

  // ---- prefetch iter-0 halo into buffer 0 ----
  {
    int tile0 = (int)blockIdx.x;
    if (tile0 < NTILES) {
      int bb = tile0 >> 10, y0 = ((tile0 >> 5) & 31) * 8, x0c = (tile0 & 31) * 8;
      const float* xb = xin + (size_t)bb * HWD * HWD * 48;
      for (int i = tid; i < 1200; i += 512) {
        int c4 = i % 12, pos = i / 12, row = pos / 10, col = pos % 10;
        int gy = y0 - 1 + row; gy = (gy < 0) ? -gy : ((gy >= HWD) ? 2 * HWD - 2 - gy : gy);
        int gx = x0c - 1 + col; gx = (gx < 0) ? -gx : ((gx >= HWD) ? 2 * HWD - 2 - gx : gx);
        CP_ASYNC16(halo_u32 + (uint32_t)((row * HROW + col * 48 + c4 * 4) * 4),
                   xb + ((size_t)gy * HWD + gx) * 48 + c4 * 4);
      }
    }
  }
  CP_COMMIT();
  __syncthreads();   // also publishes weights/filters

  int pb = 0;

  for (int iter = 0; iter < niter; iter++) {
    int tile = iter * (int)gridDim.x + (int)blockIdx.x;
    if (tile >= NTILES) break;

    const int bb = tile >> 10;
    const int y0 = ((tile >> 5) & 31) * 8;
    const int x0c = (tile & 31) * 8;

    CP_WAIT0();
    __syncthreads();            // halo[pb] ready; prev epilogue done

    const float* hstage = sm + F_HALO + pb * HALO_F;

    // ---- x-copy: P[pix][k<48] fp16 (from staged float4) ----
    {
      int pix = tid >> 3, c4 = (tid & 7);
      int py = pix >> 3, px = pix & 7;
      int base = (py + 1) * HROW + (px + 1) * 48;
      #pragma unroll
      for (int rep = 0; rep < 2; rep++) {
        int cc4 = c4 + rep * 8;
        if (cc4 < 12) {
          const float4 v = *(const float4*)&hstage[base + cc4 * 4];
          uint2 u; u.x = packh2(v.x, v.y); u.y = packh2(v.z, v.w);
          *(uint2*)&Ph[pix * PSH + cc4 * 4] = u;
        }
      }
    }
    // ---- depthwise convs: 192 merged tasks = (py-pair 0..3, ch 0..47) ----
    // each task: both filters, 2 pixel rows, 8 px -> 40 loads, 32 stores
    if (tid < 192) {
      int ch = tid % 48, pyb = (tid / 48) * 2;
      float v[4][10];
      #pragma unroll
      for (int dy = 0; dy < 4; dy++)
        #pragma unroll
        for (int q = 0; q < 10; q++)
          v[dy][q] = hstage[(pyb + dy) * HROW + q * 48 + ch];
      #pragma unroll
      for (int f = 0; f < 2; f++) {
        const float* cf = sfilt + (f * 48 + ch) * 9;
        float w[9];
        #pragma unroll
        for (int e = 0; e < 9; e++) w[e] = cf[e];
        int K = 48 + f * 48 + ch;
        #pragma unroll
        for (int p2 = 0; p2 < 2; p2++) {
          float acc[8] = {0.f,0.f,0.f,0.f,0.f,0.f,0.f,0.f};
          #pragma unroll
          for (int dy = 0; dy < 3; dy++)
            #pragma unroll
            for (int dx = 0; dx < 3; dx++) {
              float ww = w[dy * 3 + dx];
              #pragma unroll
              for (int i = 0; i < 8; i++)
                acc[i] = fmaf(v[p2 + dy][i + dx], ww, acc[i]);
            }
          #pragma unroll
          for (int i = 0; i < 8; i++)
            Ph[((pyb + p2) * 8 + i) * PSH + K] = __float2half_rn(acc[i]);
        }
      }
    }
    // ---- fire mask ----
    if (tid >= 448) {           // last 2 warps (idle in conv) do threefry
      int p = tid - 448;
      int py = p >> 3, px = p & 7;
      uint32_t n = ((uint32_t)bb * HWD + (uint32_t)(y0 + py)) * HWD + (uint32_t)(x0c + px);
      uint32_t r0, r1;
      threefry2x32(key0, key1, 0u, n, r0, r1);
      float u = __uint_as_float(((r0 ^ r1) >> 9) | 0x3f800000u) - 1.0f;
      sfire[p] = (u > 0.5f) ? 1.0f : 0.0f;
    }

    // ---- prefetch next tile's halo into buffer pb^1 (overlaps GEMMs) ----
    {
      int ntile = tile + (int)gridDim.x;
      if (ntile < NTILES) {
        int nbb = ntile >> 10, ny0 = ((ntile >> 5) & 31) * 8, nx0 = (ntile & 31) * 8;
        const float* nxb = xin + (size_t)nbb * HWD * HWD * 48;
        uint32_t dbase = halo_u32 + (uint32_t)((pb ^ 1) * HALO_F * 4);
        for (int i = tid; i < 1200; i += 512) {
          int c4 = i % 12, pos = i / 12, row = pos / 10, col = pos % 10;
          int gy = ny0 - 1 + row; gy = (gy < 0) ? -gy : ((gy >= HWD) ? 2 * HWD - 2 - gy : gy);
          int gx = nx0 - 1 + col; gx = (gx < 0) ? -gx : ((gx >= HWD) ? 2 * HWD - 2 - gx : gx);
          CP_ASYNC16(dbase + (uint32_t)((row * HROW + col * 48 + c4 * 4) * 4),
                     nxb + ((size_t)gy * HWD + gx) * 48 + c4 * 4);
        }
      }
    }
    CP_COMMIT();
    __syncthreads();            // Ph + fire ready

    // ---- GEMM1: warp = (N-32 x M-32), 9 ksteps of k16 ----
    {
      float acc[2][4][4];
      #pragma unroll
      for (int mc = 0; mc < 2; mc++)
        #pragma unroll
        for (int nb = 0; nb < 4; nb++)
          #pragma unroll
          for (int e = 0; e < 4; e++) acc[mc][nb][e] = 0.f;

      #pragma unroll
      for (int ks = 0; ks < 9; ks++) {
        uint32_t b[4][2];
        LDS_V4(b[0][0], b[0][1], b[1][0], b[1][1], b1base + ks * 8192);
        LDS_V4(b[2][0], b[2][1], b[3][0], b[3][1], b1base + ks * 8192 + 512);
        #pragma unroll
        for (int mc = 0; mc < 2; mc++) {
          uint32_t a0, a1, a2, a3;
          LDMATRIX_X4(a0, a1, a2, a3, a1base[mc] + ks * 32);
          #pragma unroll
          for (int nb = 0; nb < 4; nb++)
            mma_f16(acc[mc][nb], a0, a1, a2, a3, b[nb][0], b[nb][1]);
        }
      }
      // epilogue1: bias + leaky -> H fp16
      #pragma unroll
      for (int mc = 0; mc < 2; mc++)
        #pragma unroll
        for (int nb = 0; nb < 4; nb++) {
          int row = mh * 32 + mc * 16 + g;
          int col = ns * 32 + nb * 8 + 2 * t;
          float b0 = sb1[col], b1v = sb1[col + 1];
          float v0 = acc[mc][nb][0] + b0;
          float v1 = acc[mc][nb][1] + b1v;
          v0 = (v0 > 0.f) ? v0 : 0.01f * v0;
          v1 = (v1 > 0.f) ? v1 : 0.01f * v1;
          *(__half2*)&Hh[row * HSH + col] = __floats2half2_rn(v0, v1);
          float v2 = acc[mc][nb][2] + b0;
          float v3 = acc[mc][nb][3] + b1v;
          v2 = (v2 > 0.f) ? v2 : 0.01f * v2;
          v3 = (v3 > 0.f) ? v3 : 0.01f * v3;
          *(__half2*)&Hh[(row + 8) * HSH + col] = __floats2half2_rn(v2, v3);
        }
    }
    __syncthreads();            // H ready

    // ---- GEMM2: warp = (M-16, N-24, K-128 half); 8 ksteps ----
    float acc2[3][4];
    #pragma unroll
    for (int nb = 0; nb < 3; nb++)
      #pragma unroll
      for (int e = 0; e < 4; e++) acc2[nb][e] = 0.f;

    #pragma unroll
    for (int ks = 0; ks < 8; ks++) {
      uint32_t b2[3][2];
      LDS_V2(b2[0][0], b2[0][1], b2base + ks * 1536);
      LDS_V2(b2[1][0], b2[1][1], b2base + ks * 1536 + 8);
      LDS_V2(b2[2][0], b2[2][1], b2base + ks * 1536 + 16);
      uint32_t a0, a1, a2, a3;
      LDMATRIX_X4(a0, a1, a2, a3, a2base + ks * 32);
      #pragma unroll
      for (int nb = 0; nb < 3; nb++)
        mma_f16(acc2[nb], a0, a1, a2, a3, b2[nb][0], b2[nb][1]);
    }

    // kh=1 warps publish partials
    if (kh == 1) {
      #pragma unroll
      for (int nb = 0; nb < 3; nb++) {
        int c = nh * 24 + nb * 8 + 2 * t;
        *(float2*)&spart[(mo * 16 + g) * SPST + c]     = make_float2(acc2[nb][0], acc2[nb][1]);
        *(float2*)&spart[(mo * 16 + g + 8) * SPST + c] = make_float2(acc2[nb][2], acc2[nb][3]);
      }
    }
    __syncthreads();

    // kh=0 warps: reduce + fire + masked residual -> gmem
    if (kh == 0) {
      #pragma unroll
      for (int nb = 0; nb < 3; nb++) {
        int c = nh * 24 + nb * 8 + 2 * t;
        #pragma unroll
        for (int hf = 0; hf < 2; hf++) {
          int pix = mo * 16 + g + hf * 8;
          int py = pix >> 3, px = pix & 7;
          float fire = sfire[pix];
          float2 pp = *(const float2*)&spart[pix * SPST + c];
          float d0 = acc2[nb][hf * 2 + 0] + pp.x;
          float d1 = acc2[nb][hf * 2 + 1] + pp.y;
          int hb = (py + 1) * HROW + (px + 1) * 48;
          float xo0 = hstage[hb + c];
          float xo1 = hstage[hb + c + 1];
          float o0 = xo0 + ((c     >= 3) ? fire * d0 : 0.f);
          float o1 = xo1 + ((c + 1 >= 3) ? fire * d1 : 0.f);
          float* op = xout + (((size_t)bb * HWD + (y0 + py)) * HWD + (x0c + px)) * 48 + c;
          *(float2*)op = make_float2(o0, o1);
        }
      }
    }
    pb ^= 1;
    // loop-top wait+sync orders epilogue reads before next prefetch overwrite
  }
}

// ---------------- launcher ----------------
extern "C" void kernel_launch(void* const* d_in, const int* in_sizes, int n_in,
                              void* d_out, int out_size)
{
  const float* x     = (const float*)d_in[0];
  const float* filt0 = (const float*)d_in[1];
  const float* filt1 = (const float*)d_in[2];
  const float* w1    = (const float*)d_in[3];
  const float* b1    = (const float*)d_in[4];
  const float* w2    = (const float*)d_in[5];

  float* xbuf = nullptr;
  cudaGetSymbolAddress((void**)&xbuf, g_xbuf);
  float* outp = (float*)d_out;

  int nsm = 148;
  cudaDeviceGetAttribute(&nsm, cudaDevAttrMultiProcessorCount, 0);

  cudaFuncSetAttribute(nca_step_mma, cudaFuncAttributeMaxDynamicSharedMemorySize,
                       (int)SMEM_BYTES);

  const float* src = x;
  for (int i = 0; i < 4; i++) {
    uint32_t f0, f1; threefry2x32(0u, 42u, 0u, (uint32_t)i, f0, f1);
    uint32_t a0, a1; threefry2x32(f0, f1, 0u, 0u, a0, a1);
    float* dst = (i & 1) ? outp : xbuf;
    if (i == 3) dst = outp;
    nca_step_mma<<<nsm, 512, SMEM_BYTES>>>(src, dst, filt0, filt1, b1, w1, w2,
                                           a0, a1);
    src = dst;
  }
}